// round 6
// baseline (speedup 1.0000x reference)
#include <cuda_runtime.h>
#include <math.h>

#define TT 2048
#define HH 4096
#define NH 32
#define HD 128
#define II 11008
#define ATTN_TOPK 16
#define MLP_TOPK 2048

// ---------------- scratch (static device allocations only) ----------------
__device__ float g_hs[TT * HH];
__device__ float g_q[TT * HH];
__device__ float g_k[TT * HH];
__device__ float g_v[TT * HH];
__device__ float g_attn[TT * HH];
__device__ float g_res2[TT * HH];
__device__ float g_hlogit[TT * NH];
__device__ float g_headmask[TT * NH];
__device__ float g_mlogit[TT * II];
__device__ float g_fcmask[TT * II];
__device__ float g_gate[TT * II];
__device__ float g_up[TT * II];

// ---------------- RMSNorm ----------------
__global__ void rmsnorm_kernel(const float* __restrict__ x,
                               const float* __restrict__ w,
                               float* __restrict__ out) {
    int row = blockIdx.x;
    const float4* x4 = (const float4*)(x + (size_t)row * HH);
    const float4* w4 = (const float4*)w;
    float s = 0.f;
    for (int i = threadIdx.x; i < HH / 4; i += 256) {
        float4 v = x4[i];
        s += v.x * v.x + v.y * v.y + v.z * v.z + v.w * v.w;
    }
    __shared__ float red[256];
    red[threadIdx.x] = s;
    __syncthreads();
    for (int o = 128; o > 0; o >>= 1) {
        if (threadIdx.x < o) red[threadIdx.x] += red[threadIdx.x + o];
        __syncthreads();
    }
    float rs = rsqrtf(red[0] / (float)HH + 1e-6f);
    float4* o4 = (float4*)(out + (size_t)row * HH);
    for (int i = threadIdx.x; i < HH / 4; i += 256) {
        float4 a = x4[i];
        float4 ww = w4[i];
        a.x = a.x * rs * ww.x;
        a.y = a.y * rs * ww.y;
        a.z = a.z * rs * ww.z;
        a.w = a.w * rs * ww.w;
        o4[i] = a;
    }
}

// ---------------- SGEMM: C[M,N] = A[M,K] * B[N,K]^T (+bias[N]) (+addsrc) ----
// Proven-numerics fp32 FFMA kernel (same math/indexing as the passing R2
// version), now double-buffered: global loads staged in regs at iteration
// top, ONE __syncthreads per K-tile. BM=BN=128, BK=16, 256 thr, 8x8/thread.
__global__ void __launch_bounds__(256) sgemm_nt_kernel(
    const float* __restrict__ A, const float* __restrict__ B,
    const float* __restrict__ bias, const float* __restrict__ addsrc,
    float* __restrict__ C, int M, int N, int K) {
    __shared__ float As[2][16][132];
    __shared__ float Bs[2][16][132];
    const int bm = blockIdx.y * 128;
    const int bn = blockIdx.x * 128;
    const int tid = threadIdx.x;
    const int tr = tid >> 4;   // 0..15
    const int tc = tid & 15;   // 0..15

    float acc[8][8];
#pragma unroll
    for (int i = 0; i < 8; i++)
#pragma unroll
        for (int j = 0; j < 8; j++) acc[i][j] = 0.f;

    const int lr = tid >> 2;        // 0..63
    const int lc = (tid & 3) * 4;   // 0,4,8,12
    const float* Aptr = A + (size_t)(bm + lr) * K + lc;
    const float* Bptr = B + (size_t)(bn + lr) * K + lc;
    const size_t rowoff = (size_t)64 * K;

    const int NKT = K / 16;

    // stage tile 0
    {
        float4 a0 = *(const float4*)(Aptr);
        float4 a1 = *(const float4*)(Aptr + rowoff);
        float4 b0 = *(const float4*)(Bptr);
        float4 b1 = *(const float4*)(Bptr + rowoff);
        As[0][lc + 0][lr] = a0.x; As[0][lc + 1][lr] = a0.y;
        As[0][lc + 2][lr] = a0.z; As[0][lc + 3][lr] = a0.w;
        As[0][lc + 0][lr + 64] = a1.x; As[0][lc + 1][lr + 64] = a1.y;
        As[0][lc + 2][lr + 64] = a1.z; As[0][lc + 3][lr + 64] = a1.w;
        Bs[0][lc + 0][lr] = b0.x; Bs[0][lc + 1][lr] = b0.y;
        Bs[0][lc + 2][lr] = b0.z; Bs[0][lc + 3][lr] = b0.w;
        Bs[0][lc + 0][lr + 64] = b1.x; Bs[0][lc + 1][lr + 64] = b1.y;
        Bs[0][lc + 2][lr + 64] = b1.z; Bs[0][lc + 3][lr + 64] = b1.w;
    }
    __syncthreads();

    for (int kt = 0; kt < NKT; kt++) {
        const int buf = kt & 1;
        const bool more = (kt + 1 < NKT);
        float4 a0n, a1n, b0n, b1n;
        if (more) {
            int k0 = (kt + 1) * 16;
            a0n = *(const float4*)(Aptr + k0);
            a1n = *(const float4*)(Aptr + k0 + rowoff);
            b0n = *(const float4*)(Bptr + k0);
            b1n = *(const float4*)(Bptr + k0 + rowoff);
        }

#pragma unroll
        for (int kk = 0; kk < 16; kk++) {
            float ra[8], rb[8];
#pragma unroll
            for (int i = 0; i < 8; i++) ra[i] = As[buf][kk][tr * 8 + i];
#pragma unroll
            for (int j = 0; j < 8; j++) rb[j] = Bs[buf][kk][tc * 8 + j];
#pragma unroll
            for (int i = 0; i < 8; i++)
#pragma unroll
                for (int j = 0; j < 8; j++)
                    acc[i][j] = fmaf(ra[i], rb[j], acc[i][j]);
        }

        if (more) {
            const int nb = buf ^ 1;
            As[nb][lc + 0][lr] = a0n.x; As[nb][lc + 1][lr] = a0n.y;
            As[nb][lc + 2][lr] = a0n.z; As[nb][lc + 3][lr] = a0n.w;
            As[nb][lc + 0][lr + 64] = a1n.x; As[nb][lc + 1][lr + 64] = a1n.y;
            As[nb][lc + 2][lr + 64] = a1n.z; As[nb][lc + 3][lr + 64] = a1n.w;
            Bs[nb][lc + 0][lr] = b0n.x; Bs[nb][lc + 1][lr] = b0n.y;
            Bs[nb][lc + 2][lr] = b0n.z; Bs[nb][lc + 3][lr] = b0n.w;
            Bs[nb][lc + 0][lr + 64] = b1n.x; Bs[nb][lc + 1][lr + 64] = b1n.y;
            Bs[nb][lc + 2][lr + 64] = b1n.z; Bs[nb][lc + 3][lr + 64] = b1n.w;
        }
        __syncthreads();
    }

#pragma unroll
    for (int i = 0; i < 8; i++) {
        int row = bm + tr * 8 + i;
        size_t base = (size_t)row * N + bn + tc * 8;
#pragma unroll
        for (int j = 0; j < 8; j += 4) {
            float4 r;
            r.x = acc[i][j + 0]; r.y = acc[i][j + 1];
            r.z = acc[i][j + 2]; r.w = acc[i][j + 3];
            if (bias) {
                int cn = bn + tc * 8 + j;
                r.x += bias[cn + 0]; r.y += bias[cn + 1];
                r.z += bias[cn + 2]; r.w += bias[cn + 3];
            }
            if (addsrc) {
                float4 s = *(const float4*)(addsrc + base + j);
                r.x += s.x; r.y += s.y; r.z += s.z; r.w += s.w;
            }
            *(float4*)(C + base + j) = r;
        }
    }
}

// ---------------- RoPE (position_ids int32) ----------------
__global__ void rope_kernel(float* __restrict__ q, float* __restrict__ k,
                            const int* __restrict__ pos) {
    int idx = blockIdx.x * 256 + threadIdx.x;
    if (idx >= TT * NH * 64) return;
    int j = idx & 63;
    int th = idx >> 6;
    int t = th >> 5;
    float p = (float)pos[t];
    float ang = p * exp2f(-(float)j * (13.287712379549449f / 64.f));
    float s, c;
    sincosf(ang, &s, &c);
    size_t base = (size_t)th * HD + j;
    float q0 = q[base], q1 = q[base + 64];
    q[base] = q0 * c - q1 * s;
    q[base + 64] = q1 * c + q0 * s;
    float k0 = k[base], k1 = k[base + 64];
    k[base] = k0 * c - k1 * s;
    k[base + 64] = k1 * c + k0 * s;
}

// ---------------- attn predictor logits ----------------
__global__ void attn_pred_kernel(const float* __restrict__ hs,
                                 const float* __restrict__ w,
                                 const float* __restrict__ b,
                                 float* __restrict__ out) {
    int t = blockIdx.x;
    int warp = threadIdx.x >> 5, lane = threadIdx.x & 31;
    const float* hsrow = hs + (size_t)t * HH;
    for (int hh = 0; hh < 4; hh++) {
        int h = warp * 4 + hh;
        const float* wr = w + (size_t)h * HH;
        float s = 0.f;
        for (int kk = lane; kk < HH; kk += 32) s += hsrow[kk] * wr[kk];
        for (int o = 16; o > 0; o >>= 1) s += __shfl_xor_sync(0xffffffffu, s, o);
        if (lane == 0) out[t * NH + h] = s + b[h];
    }
}

// ---------------- head top-16 mask ----------------
__global__ void head_mask_kernel(const float* __restrict__ logit,
                                 float* __restrict__ mask) {
    int t = blockIdx.x;
    int h = threadIdx.x;
    float v = logit[t * NH + h];
    int rank = 0;
    for (int j = 0; j < NH; j++) {
        float vj = logit[t * NH + j];
        rank += (vj > v) || (vj == v && j < h);
    }
    mask[t * NH + h] = (rank < ATTN_TOPK) ? 1.f : 0.f;
}

// ---------------- attention ----------------
__global__ void attention_kernel(const float* __restrict__ q,
                                 const float* __restrict__ k,
                                 const float* __restrict__ v,
                                 const float* __restrict__ hmask,
                                 const int* __restrict__ amask,
                                 float* __restrict__ out) {
    int t = blockIdx.x, h = blockIdx.y, tid = threadIdx.x;
    size_t obase = (size_t)t * HH + h * HD;
    if (hmask[t * NH + h] == 0.f) {
        out[obase + tid] = 0.f;
        return;
    }
    __shared__ float qs[HD];
    __shared__ float p[TT];
    __shared__ float red[128];
    qs[tid] = q[obase + tid] * 0.08838834764831845f;
    __syncthreads();
    int nk = t + 1;
    const float NEGF = -3.4e38f;
    float lm = NEGF;
    for (int j = tid; j < nk; j += 128) {
        float s;
        if (amask[j]) {
            const float4* kr = (const float4*)(k + (size_t)j * HH + h * HD);
            s = 0.f;
#pragma unroll
            for (int d4 = 0; d4 < 32; d4++) {
                float4 kv = kr[d4];
                s += qs[4 * d4 + 0] * kv.x + qs[4 * d4 + 1] * kv.y +
                     qs[4 * d4 + 2] * kv.z + qs[4 * d4 + 3] * kv.w;
            }
        } else {
            s = NEGF;
        }
        p[j] = s;
        lm = fmaxf(lm, s);
    }
    red[tid] = lm;
    __syncthreads();
    for (int o = 64; o > 0; o >>= 1) {
        if (tid < o) red[tid] = fmaxf(red[tid], red[tid + o]);
        __syncthreads();
    }
    float M = red[0];
    __syncthreads();
    float ls = 0.f;
    for (int j = tid; j < nk; j += 128) {
        float e = __expf(p[j] - M);
        p[j] = e;
        ls += e;
    }
    red[tid] = ls;
    __syncthreads();
    for (int o = 64; o > 0; o >>= 1) {
        if (tid < o) red[tid] += red[tid + o];
        __syncthreads();
    }
    float inv = 1.f / red[0];
    __syncthreads();
    float acc = 0.f;
#pragma unroll 4
    for (int j = 0; j < nk; j++)
        acc = fmaf(p[j], v[(size_t)j * HH + h * HD + tid], acc);
    out[obase + tid] = acc * inv;
}

// ---------------- MLP top-2048 radix select ----------------
__device__ __forceinline__ unsigned fkey(float x) {
    unsigned b = __float_as_uint(x);
    return (b & 0x80000000u) ? ~b : (b | 0x80000000u);
}

__global__ void mlp_topk_kernel(const float* __restrict__ logits,
                                float* __restrict__ mask) {
    int row = blockIdx.x;
    const float* lr = logits + (size_t)row * II;
    __shared__ unsigned hist[256];
    __shared__ unsigned sh_sel, sh_kk;
    __shared__ unsigned sh_cnt[2];
    int tid = threadIdx.x;
    unsigned prefix = 0;
    unsigned kk = MLP_TOPK;
    for (int shift = 24; shift >= 0; shift -= 8) {
        hist[tid] = 0;
        __syncthreads();
        for (int i = tid; i < II; i += 256) {
            unsigned u = fkey(lr[i]);
            bool ok = (shift == 24) || ((u >> (shift + 8)) == prefix);
            if (ok) atomicAdd(&hist[(u >> shift) & 255u], 1u);
        }
        __syncthreads();
        if (tid == 0) {
            unsigned c = 0;
            int sel = 0;
            for (int b = 255; b >= 0; b--) {
                c += hist[b];
                if (c >= kk) { sel = b; break; }
            }
            sh_sel = (unsigned)sel;
            sh_kk = kk - (c - hist[sel]);
        }
        __syncthreads();
        prefix = (prefix << 8) | sh_sel;
        kk = sh_kk;
        __syncthreads();
    }
    unsigned thresh = prefix;
    if (tid < 2) sh_cnt[tid] = 0;
    __syncthreads();
    unsigned lg = 0, le = 0;
    for (int i = tid; i < II; i += 256) {
        unsigned u = fkey(lr[i]);
        if (u > thresh) lg++;
        else if (u == thresh) le++;
    }
    atomicAdd(&sh_cnt[0], lg);
    atomicAdd(&sh_cnt[1], le);
    __syncthreads();
    unsigned g = sh_cnt[0], e = sh_cnt[1];
    float* mr = mask + (size_t)row * II;
    if (g + e == MLP_TOPK) {
        for (int i = tid; i < II; i += 256)
            mr[i] = (fkey(lr[i]) >= thresh) ? 1.f : 0.f;
    } else {
        for (int i = tid; i < II; i += 256)
            mr[i] = (fkey(lr[i]) > thresh) ? 1.f : 0.f;
        __syncthreads();
        if (tid == 0) {
            unsigned quota = MLP_TOPK - g;
            for (int i = 0; i < II && quota > 0; i++) {
                if (fkey(lr[i]) == thresh) { mr[i] = 1.f; quota--; }
            }
        }
    }
}

// ---------------- silu * up * mask ----------------
__global__ void silu_mul_mask_kernel(float* __restrict__ gate,
                                     const float* __restrict__ up,
                                     const float* __restrict__ mask, int n) {
    int i = blockIdx.x * 256 + threadIdx.x;
    if (i < n) {
        float x = gate[i];
        float si = x / (1.f + __expf(-x));
        gate[i] = si * up[i] * mask[i];
    }
}

// ---------------- launch ----------------
extern "C" void kernel_launch(void* const* d_in, const int* in_sizes, int n_in,
                              void* d_out, int out_size) {
    const float* hidden = (const float*)d_in[0];
    const int* amask = (const int*)d_in[1];
    const int* pos = (const int*)d_in[2];
    const float* wq = (const float*)d_in[3];
    const float* wk = (const float*)d_in[4];
    const float* wv = (const float*)d_in[5];
    const float* wo = (const float*)d_in[6];
    const float* w_gate = (const float*)d_in[7];
    const float* w_up = (const float*)d_in[8];
    const float* w_down = (const float*)d_in[9];
    const float* ln1 = (const float*)d_in[10];
    const float* ln2 = (const float*)d_in[11];
    const float* apw = (const float*)d_in[12];
    const float* apb = (const float*)d_in[13];
    const float* mpw = (const float*)d_in[14];
    const float* mpb = (const float*)d_in[15];
    float* out = (float*)d_out;

    float *hs, *q, *k, *v, *attn, *res2, *hlog, *hmask, *mlog, *fcm, *gate, *up;
    cudaGetSymbolAddress((void**)&hs, g_hs);
    cudaGetSymbolAddress((void**)&q, g_q);
    cudaGetSymbolAddress((void**)&k, g_k);
    cudaGetSymbolAddress((void**)&v, g_v);
    cudaGetSymbolAddress((void**)&attn, g_attn);
    cudaGetSymbolAddress((void**)&res2, g_res2);
    cudaGetSymbolAddress((void**)&hlog, g_hlogit);
    cudaGetSymbolAddress((void**)&hmask, g_headmask);
    cudaGetSymbolAddress((void**)&mlog, g_mlogit);
    cudaGetSymbolAddress((void**)&fcm, g_fcmask);
    cudaGetSymbolAddress((void**)&gate, g_gate);
    cudaGetSymbolAddress((void**)&up, g_up);

    dim3 gHH(HH / 128, TT / 128);
    dim3 gII(II / 128, TT / 128);

    rmsnorm_kernel<<<TT, 256>>>(hidden, ln1, hs);
    sgemm_nt_kernel<<<gHH, 256>>>(hs, wq, nullptr, nullptr, q, TT, HH, HH);
    sgemm_nt_kernel<<<gHH, 256>>>(hs, wk, nullptr, nullptr, k, TT, HH, HH);
    sgemm_nt_kernel<<<gHH, 256>>>(hs, wv, nullptr, nullptr, v, TT, HH, HH);
    rope_kernel<<<(TT * NH * 64 + 255) / 256, 256>>>(q, k, pos);
    attn_pred_kernel<<<TT, 256>>>(hs, apw, apb, hlog);
    head_mask_kernel<<<TT, 32>>>(hlog, hmask);
    attention_kernel<<<dim3(TT, NH), 128>>>(q, k, v, hmask, amask, attn);
    sgemm_nt_kernel<<<gHH, 256>>>(attn, wo, nullptr, hidden, res2, TT, HH, HH);
    rmsnorm_kernel<<<TT, 256>>>(res2, ln2, hs);
    sgemm_nt_kernel<<<gII, 256>>>(hs, mpw, mpb, nullptr, mlog, TT, II, HH);
    mlp_topk_kernel<<<TT, 256>>>(mlog, fcm);
    sgemm_nt_kernel<<<gII, 256>>>(hs, w_gate, nullptr, nullptr, gate, TT, II, HH);
    sgemm_nt_kernel<<<gII, 256>>>(hs, w_up, nullptr, nullptr, up, TT, II, HH);
    silu_mul_mask_kernel<<<(TT * II + 255) / 256, 256>>>(gate, up, fcm, TT * II);
    sgemm_nt_kernel<<<gHH, 256>>>(gate, w_down, nullptr, res2, out, TT, HH, II);
}

// round 8
// speedup vs baseline: 1.5258x; 1.5258x over previous
#include <cuda_runtime.h>
#include <cuda_bf16.h>
#include <math.h>
#include <stdint.h>

#define TT 2048
#define HH 4096
#define NH 32
#define HD 128
#define II 11008
#define ATTN_TOPK 16
#define MLP_TOPK 2048

// ---------------- scratch ----------------
__device__ float g_hs[TT * HH];
__device__ float g_q[TT * HH];
__device__ float g_k[TT * HH];
__device__ float g_v[TT * HH];
__device__ float g_attn[TT * HH];
__device__ float g_res2[TT * HH];
__device__ float g_hlogit[TT * NH];
__device__ float g_headmask[TT * NH];
__device__ float g_mlogit[TT * II];
__device__ float g_fcmask[TT * II];
__device__ float g_gate[TT * II];
__device__ float g_up[TT * II];

// ---------------- RMSNorm ----------------
__global__ void rmsnorm_kernel(const float* __restrict__ x,
                               const float* __restrict__ w,
                               float* __restrict__ out) {
    int row = blockIdx.x;
    const float4* x4 = (const float4*)(x + (size_t)row * HH);
    const float4* w4 = (const float4*)w;
    float s = 0.f;
    for (int i = threadIdx.x; i < HH / 4; i += 256) {
        float4 v = x4[i];
        s += v.x * v.x + v.y * v.y + v.z * v.z + v.w * v.w;
    }
    __shared__ float red[256];
    red[threadIdx.x] = s;
    __syncthreads();
    for (int o = 128; o > 0; o >>= 1) {
        if (threadIdx.x < o) red[threadIdx.x] += red[threadIdx.x + o];
        __syncthreads();
    }
    float rs = rsqrtf(red[0] / (float)HH + 1e-6f);
    float4* o4 = (float4*)(out + (size_t)row * HH);
    for (int i = threadIdx.x; i < HH / 4; i += 256) {
        float4 a = x4[i];
        float4 ww = w4[i];
        a.x = a.x * rs * ww.x;
        a.y = a.y * rs * ww.y;
        a.z = a.z * rs * ww.z;
        a.w = a.w * rs * ww.w;
        o4[i] = a;
    }
}

// ---------------- exact fp32 SGEMM (proven R2 config: single-buffer) -------
// C[M,N] = A[M,K]*B[N,K]^T (+bias[N]) (+addsrc). BM=BN=128, BK=16, 256 thr.
__global__ void __launch_bounds__(256) sgemm_nt_kernel(
    const float* __restrict__ A, const float* __restrict__ B,
    const float* __restrict__ bias, const float* __restrict__ addsrc,
    float* __restrict__ C, int M, int N, int K) {
    __shared__ float As[16][132];
    __shared__ float Bs[16][132];
    const int bm = blockIdx.y * 128;
    const int bn = blockIdx.x * 128;
    const int tid = threadIdx.x;
    const int tr = tid >> 4;
    const int tc = tid & 15;

    float acc[8][8];
#pragma unroll
    for (int i = 0; i < 8; i++)
#pragma unroll
        for (int j = 0; j < 8; j++) acc[i][j] = 0.f;

    const int lr = tid >> 2;
    const int lc = (tid & 3) * 4;
    const float* Aptr = A + (size_t)(bm + lr) * K + lc;
    const float* Bptr = B + (size_t)(bn + lr) * K + lc;
    const size_t rowoff = (size_t)64 * K;

    for (int k0 = 0; k0 < K; k0 += 16) {
        float4 a0 = *(const float4*)(Aptr + k0);
        float4 a1 = *(const float4*)(Aptr + k0 + rowoff);
        float4 b0 = *(const float4*)(Bptr + k0);
        float4 b1 = *(const float4*)(Bptr + k0 + rowoff);
        As[lc + 0][lr] = a0.x; As[lc + 1][lr] = a0.y;
        As[lc + 2][lr] = a0.z; As[lc + 3][lr] = a0.w;
        As[lc + 0][lr + 64] = a1.x; As[lc + 1][lr + 64] = a1.y;
        As[lc + 2][lr + 64] = a1.z; As[lc + 3][lr + 64] = a1.w;
        Bs[lc + 0][lr] = b0.x; Bs[lc + 1][lr] = b0.y;
        Bs[lc + 2][lr] = b0.z; Bs[lc + 3][lr] = b0.w;
        Bs[lc + 0][lr + 64] = b1.x; Bs[lc + 1][lr + 64] = b1.y;
        Bs[lc + 2][lr + 64] = b1.z; Bs[lc + 3][lr + 64] = b1.w;
        __syncthreads();
#pragma unroll
        for (int kk = 0; kk < 16; kk++) {
            float ra[8], rb[8];
#pragma unroll
            for (int i = 0; i < 8; i++) ra[i] = As[kk][tr * 8 + i];
#pragma unroll
            for (int j = 0; j < 8; j++) rb[j] = Bs[kk][tc * 8 + j];
#pragma unroll
            for (int i = 0; i < 8; i++)
#pragma unroll
                for (int j = 0; j < 8; j++)
                    acc[i][j] = fmaf(ra[i], rb[j], acc[i][j]);
        }
        __syncthreads();
    }

#pragma unroll
    for (int i = 0; i < 8; i++) {
        int row = bm + tr * 8 + i;
        size_t base = (size_t)row * N + bn + tc * 8;
#pragma unroll
        for (int j = 0; j < 8; j += 4) {
            float4 r;
            r.x = acc[i][j + 0]; r.y = acc[i][j + 1];
            r.z = acc[i][j + 2]; r.w = acc[i][j + 3];
            if (bias) {
                int cn = bn + tc * 8 + j;
                r.x += bias[cn + 0]; r.y += bias[cn + 1];
                r.z += bias[cn + 2]; r.w += bias[cn + 3];
            }
            if (addsrc) {
                float4 s = *(const float4*)(addsrc + base + j);
                r.x += s.x; r.y += s.y; r.z += s.z; r.w += s.w;
            }
            *(float4*)(C + base + j) = r;
        }
    }
}

// ================= bf16x3 mma GEMM (gate/up/down only) =====================
__device__ __forceinline__ uint32_t packbf(__nv_bfloat16 a, __nv_bfloat16 b) {
    __nv_bfloat162 t;
    t.x = a; t.y = b;
    return *(uint32_t*)&t;
}

__device__ __forceinline__ void split4(float4 v, uint2& hi, uint2& lo) {
    __nv_bfloat16 hx = __float2bfloat16(v.x);
    __nv_bfloat16 hy = __float2bfloat16(v.y);
    __nv_bfloat16 hz = __float2bfloat16(v.z);
    __nv_bfloat16 hw = __float2bfloat16(v.w);
    __nv_bfloat16 lx = __float2bfloat16(v.x - __bfloat162float(hx));
    __nv_bfloat16 ly = __float2bfloat16(v.y - __bfloat162float(hy));
    __nv_bfloat16 lz = __float2bfloat16(v.z - __bfloat162float(hz));
    __nv_bfloat16 lw = __float2bfloat16(v.w - __bfloat162float(hw));
    hi.x = packbf(hx, hy); hi.y = packbf(hz, hw);
    lo.x = packbf(lx, ly); lo.y = packbf(lz, lw);
}

__device__ __forceinline__ void mma16(float* c, uint32_t a0, uint32_t a1,
                                      uint32_t a2, uint32_t a3,
                                      uint32_t b0, uint32_t b1) {
    asm volatile(
        "mma.sync.aligned.m16n8k16.row.col.f32.bf16.bf16.f32 "
        "{%0,%1,%2,%3}, {%4,%5,%6,%7}, {%8,%9}, {%0,%1,%2,%3};"
        : "+f"(c[0]), "+f"(c[1]), "+f"(c[2]), "+f"(c[3])
        : "r"(a0), "r"(a1), "r"(a2), "r"(a3), "r"(b0), "r"(b1));
}

#define STRH 40
#define HBUF (128 * STRH)

__global__ void __launch_bounds__(256) bf16x3gemm_nt(
    const float* __restrict__ A, const float* __restrict__ B,
    const float* __restrict__ bias, const float* __restrict__ addsrc,
    float* __restrict__ C, int M, int N, int K) {
    extern __shared__ __nv_bfloat16 sh[];
    __nv_bfloat16* Ah = sh;
    __nv_bfloat16* Al = sh + 2 * HBUF;
    __nv_bfloat16* Bh = sh + 4 * HBUF;
    __nv_bfloat16* Bl = sh + 6 * HBUF;

    const int tid = threadIdx.x;
    const int lane = tid & 31;
    const int warp = tid >> 5;
    const int wm = warp & 1;
    const int wn = warp >> 1;
    const int g = lane >> 2;
    const int tg = lane & 3;
    const int bm = blockIdx.y * 128;
    const int bn = blockIdx.x * 128;

    float acc[4][4][4];
#pragma unroll
    for (int i = 0; i < 4; i++)
#pragma unroll
        for (int j = 0; j < 4; j++)
#pragma unroll
            for (int l = 0; l < 4; l++) acc[i][j][l] = 0.f;

    const int lrow = tid >> 3;
    const int lc4 = (tid & 7) * 4;
    const float* Ag = A + (size_t)(bm + lrow) * K + lc4;
    const float* Bg = B + (size_t)(bn + lrow) * K + lc4;

    float4 pa[4], pb[4];
#pragma unroll
    for (int p = 0; p < 4; p++) {
        pa[p] = *(const float4*)(Ag + (size_t)(p * 32) * K);
        pb[p] = *(const float4*)(Bg + (size_t)(p * 32) * K);
    }

    const int NKT = K / 32;

#pragma unroll
    for (int p = 0; p < 4; p++) {
        int row = lrow + p * 32;
        uint2 hi, lo;
        split4(pa[p], hi, lo);
        *(uint2*)(Ah + row * STRH + lc4) = hi;
        *(uint2*)(Al + row * STRH + lc4) = lo;
        split4(pb[p], hi, lo);
        *(uint2*)(Bh + row * STRH + lc4) = hi;
        *(uint2*)(Bl + row * STRH + lc4) = lo;
    }
    __syncthreads();

    for (int kt = 0; kt < NKT; kt++) {
        const int cur = kt & 1;
        const bool more = (kt + 1 < NKT);
        if (more) {
            size_t off = (size_t)(kt + 1) * 32;
#pragma unroll
            for (int p = 0; p < 4; p++) {
                pa[p] = *(const float4*)(Ag + (size_t)(p * 32) * K + off);
                pb[p] = *(const float4*)(Bg + (size_t)(p * 32) * K + off);
            }
        }
        const __nv_bfloat16* Ach = Ah + cur * HBUF;
        const __nv_bfloat16* Acl = Al + cur * HBUF;
        const __nv_bfloat16* Bch = Bh + cur * HBUF;
        const __nv_bfloat16* Bcl = Bl + cur * HBUF;

#pragma unroll
        for (int ks = 0; ks < 2; ks++) {
            const int k = ks * 16;
            uint32_t afh[4][4], afl[4][4], bfh[4][2], bfl[4][2];
#pragma unroll
            for (int mi = 0; mi < 4; mi++) {
                int rb = wm * 64 + mi * 16;
                int i00 = (rb + g) * STRH + k + 2 * tg;
                int i01 = (rb + 8 + g) * STRH + k + 2 * tg;
                afh[mi][0] = *(const uint32_t*)(Ach + i00);
                afh[mi][1] = *(const uint32_t*)(Ach + i01);
                afh[mi][2] = *(const uint32_t*)(Ach + i00 + 8);
                afh[mi][3] = *(const uint32_t*)(Ach + i01 + 8);
                afl[mi][0] = *(const uint32_t*)(Acl + i00);
                afl[mi][1] = *(const uint32_t*)(Acl + i01);
                afl[mi][2] = *(const uint32_t*)(Acl + i00 + 8);
                afl[mi][3] = *(const uint32_t*)(Acl + i01 + 8);
            }
#pragma unroll
            for (int ni = 0; ni < 4; ni++) {
                int nb = wn * 32 + ni * 8;
                int j0 = (nb + g) * STRH + k + 2 * tg;
                bfh[ni][0] = *(const uint32_t*)(Bch + j0);
                bfh[ni][1] = *(const uint32_t*)(Bch + j0 + 8);
                bfl[ni][0] = *(const uint32_t*)(Bcl + j0);
                bfl[ni][1] = *(const uint32_t*)(Bcl + j0 + 8);
            }
#pragma unroll
            for (int mi = 0; mi < 4; mi++)
#pragma unroll
                for (int ni = 0; ni < 4; ni++) {
                    mma16(acc[mi][ni], afh[mi][0], afh[mi][1], afh[mi][2],
                          afh[mi][3], bfh[ni][0], bfh[ni][1]);
                    mma16(acc[mi][ni], afh[mi][0], afh[mi][1], afh[mi][2],
                          afh[mi][3], bfl[ni][0], bfl[ni][1]);
                    mma16(acc[mi][ni], afl[mi][0], afl[mi][1], afl[mi][2],
                          afl[mi][3], bfh[ni][0], bfh[ni][1]);
                }
        }

        if (more) {
            const int nxt = (kt + 1) & 1;
            __nv_bfloat16* Adh = Ah + nxt * HBUF;
            __nv_bfloat16* Adl = Al + nxt * HBUF;
            __nv_bfloat16* Bdh = Bh + nxt * HBUF;
            __nv_bfloat16* Bdl = Bl + nxt * HBUF;
#pragma unroll
            for (int p = 0; p < 4; p++) {
                int row = lrow + p * 32;
                uint2 hi, lo;
                split4(pa[p], hi, lo);
                *(uint2*)(Adh + row * STRH + lc4) = hi;
                *(uint2*)(Adl + row * STRH + lc4) = lo;
                split4(pb[p], hi, lo);
                *(uint2*)(Bdh + row * STRH + lc4) = hi;
                *(uint2*)(Bdl + row * STRH + lc4) = lo;
            }
        }
        __syncthreads();
    }

#pragma unroll
    for (int mi = 0; mi < 4; mi++) {
        int r0 = bm + wm * 64 + mi * 16 + g;
#pragma unroll
        for (int ni = 0; ni < 4; ni++) {
            int col = bn + wn * 32 + ni * 8 + tg * 2;
            float2 v0, v1;
            v0.x = acc[mi][ni][0]; v0.y = acc[mi][ni][1];
            v1.x = acc[mi][ni][2]; v1.y = acc[mi][ni][3];
            if (bias) {
                float2 bb = *(const float2*)(bias + col);
                v0.x += bb.x; v0.y += bb.y;
                v1.x += bb.x; v1.y += bb.y;
            }
            size_t i0 = (size_t)r0 * N + col;
            size_t i1 = (size_t)(r0 + 8) * N + col;
            if (addsrc) {
                float2 s0 = *(const float2*)(addsrc + i0);
                float2 s1 = *(const float2*)(addsrc + i1);
                v0.x += s0.x; v0.y += s0.y;
                v1.x += s1.x; v1.y += s1.y;
            }
            *(float2*)(C + i0) = v0;
            *(float2*)(C + i1) = v1;
        }
    }
}

// ---------------- RoPE (position_ids int32) ----------------
__global__ void rope_kernel(float* __restrict__ q, float* __restrict__ k,
                            const int* __restrict__ pos) {
    int idx = blockIdx.x * 256 + threadIdx.x;
    if (idx >= TT * NH * 64) return;
    int j = idx & 63;
    int th = idx >> 6;
    int t = th >> 5;
    float p = (float)pos[t];
    float ang = p * exp2f(-(float)j * (13.287712379549449f / 64.f));
    float s, c;
    sincosf(ang, &s, &c);
    size_t base = (size_t)th * HD + j;
    float q0 = q[base], q1 = q[base + 64];
    q[base] = q0 * c - q1 * s;
    q[base + 64] = q1 * c + q0 * s;
    float k0 = k[base], k1 = k[base + 64];
    k[base] = k0 * c - k1 * s;
    k[base + 64] = k1 * c + k0 * s;
}

// ---------------- attn predictor logits ----------------
__global__ void attn_pred_kernel(const float* __restrict__ hs,
                                 const float* __restrict__ w,
                                 const float* __restrict__ b,
                                 float* __restrict__ out) {
    int t = blockIdx.x;
    int warp = threadIdx.x >> 5, lane = threadIdx.x & 31;
    const float* hsrow = hs + (size_t)t * HH;
    for (int hh = 0; hh < 4; hh++) {
        int h = warp * 4 + hh;
        const float* wr = w + (size_t)h * HH;
        float s = 0.f;
        for (int kk = lane; kk < HH; kk += 32) s += hsrow[kk] * wr[kk];
        for (int o = 16; o > 0; o >>= 1) s += __shfl_xor_sync(0xffffffffu, s, o);
        if (lane == 0) out[t * NH + h] = s + b[h];
    }
}

// ---------------- head top-16 mask ----------------
__global__ void head_mask_kernel(const float* __restrict__ logit,
                                 float* __restrict__ mask) {
    int t = blockIdx.x;
    int h = threadIdx.x;
    float v = logit[t * NH + h];
    int rank = 0;
    for (int j = 0; j < NH; j++) {
        float vj = logit[t * NH + j];
        rank += (vj > v) || (vj == v && j < h);
    }
    mask[t * NH + h] = (rank < ATTN_TOPK) ? 1.f : 0.f;
}

// ---------------- attention ----------------
__global__ void attention_kernel(const float* __restrict__ q,
                                 const float* __restrict__ k,
                                 const float* __restrict__ v,
                                 const float* __restrict__ hmask,
                                 const int* __restrict__ amask,
                                 float* __restrict__ out) {
    int t = blockIdx.x, h = blockIdx.y, tid = threadIdx.x;
    size_t obase = (size_t)t * HH + h * HD;
    if (hmask[t * NH + h] == 0.f) {
        out[obase + tid] = 0.f;
        return;
    }
    __shared__ float qs[HD];
    __shared__ float p[TT];
    __shared__ float red[128];
    qs[tid] = q[obase + tid] * 0.08838834764831845f;
    __syncthreads();
    int nk = t + 1;
    const float NEGF = -3.4e38f;
    float lm = NEGF;
    for (int j = tid; j < nk; j += 128) {
        float s;
        if (amask[j]) {
            const float4* kr = (const float4*)(k + (size_t)j * HH + h * HD);
            s = 0.f;
#pragma unroll
            for (int d4 = 0; d4 < 32; d4++) {
                float4 kv = kr[d4];
                s += qs[4 * d4 + 0] * kv.x + qs[4 * d4 + 1] * kv.y +
                     qs[4 * d4 + 2] * kv.z + qs[4 * d4 + 3] * kv.w;
            }
        } else {
            s = NEGF;
        }
        p[j] = s;
        lm = fmaxf(lm, s);
    }
    red[tid] = lm;
    __syncthreads();
    for (int o = 64; o > 0; o >>= 1) {
        if (tid < o) red[tid] = fmaxf(red[tid], red[tid + o]);
        __syncthreads();
    }
    float M = red[0];
    __syncthreads();
    float ls = 0.f;
    for (int j = tid; j < nk; j += 128) {
        float e = __expf(p[j] - M);
        p[j] = e;
        ls += e;
    }
    red[tid] = ls;
    __syncthreads();
    for (int o = 64; o > 0; o >>= 1) {
        if (tid < o) red[tid] += red[tid + o];
        __syncthreads();
    }
    float inv = 1.f / red[0];
    __syncthreads();
    float acc = 0.f;
#pragma unroll 4
    for (int j = 0; j < nk; j++)
        acc = fmaf(p[j], v[(size_t)j * HH + h * HD + tid], acc);
    out[obase + tid] = acc * inv;
}

// ---------------- MLP top-2048 radix select ----------------
__device__ __forceinline__ unsigned fkey(float x) {
    unsigned b = __float_as_uint(x);
    return (b & 0x80000000u) ? ~b : (b | 0x80000000u);
}

__global__ void mlp_topk_kernel(const float* __restrict__ logits,
                                float* __restrict__ mask) {
    int row = blockIdx.x;
    const float* lr = logits + (size_t)row * II;
    __shared__ unsigned hist[256];
    __shared__ unsigned sh_sel, sh_kk;
    __shared__ unsigned sh_cnt[2];
    int tid = threadIdx.x;
    unsigned prefix = 0;
    unsigned kk = MLP_TOPK;
    for (int shift = 24; shift >= 0; shift -= 8) {
        hist[tid] = 0;
        __syncthreads();
        for (int i = tid; i < II; i += 256) {
            unsigned u = fkey(lr[i]);
            bool ok = (shift == 24) || ((u >> (shift + 8)) == prefix);
            if (ok) atomicAdd(&hist[(u >> shift) & 255u], 1u);
        }
        __syncthreads();
        if (tid == 0) {
            unsigned c = 0;
            int sel = 0;
            for (int b = 255; b >= 0; b--) {
                c += hist[b];
                if (c >= kk) { sel = b; break; }
            }
            sh_sel = (unsigned)sel;
            sh_kk = kk - (c - hist[sel]);
        }
        __syncthreads();
        prefix = (prefix << 8) | sh_sel;
        kk = sh_kk;
        __syncthreads();
    }
    unsigned thresh = prefix;
    if (tid < 2) sh_cnt[tid] = 0;
    __syncthreads();
    unsigned lg = 0, le = 0;
    for (int i = tid; i < II; i += 256) {
        unsigned u = fkey(lr[i]);
        if (u > thresh) lg++;
        else if (u == thresh) le++;
    }
    atomicAdd(&sh_cnt[0], lg);
    atomicAdd(&sh_cnt[1], le);
    __syncthreads();
    unsigned g = sh_cnt[0], e = sh_cnt[1];
    float* mr = mask + (size_t)row * II;
    if (g + e == MLP_TOPK) {
        for (int i = tid; i < II; i += 256)
            mr[i] = (fkey(lr[i]) >= thresh) ? 1.f : 0.f;
    } else {
        for (int i = tid; i < II; i += 256)
            mr[i] = (fkey(lr[i]) > thresh) ? 1.f : 0.f;
        __syncthreads();
        if (tid == 0) {
            unsigned quota = MLP_TOPK - g;
            for (int i = 0; i < II && quota > 0; i++) {
                if (fkey(lr[i]) == thresh) { mr[i] = 1.f; quota--; }
            }
        }
    }
}

// ---------------- silu * up * mask ----------------
__global__ void silu_mul_mask_kernel(float* __restrict__ gate,
                                     const float* __restrict__ up,
                                     const float* __restrict__ mask, int n) {
    int i = blockIdx.x * 256 + threadIdx.x;
    if (i < n) {
        float x = gate[i];
        float si = x / (1.f + __expf(-x));
        gate[i] = si * up[i] * mask[i];
    }
}

// ---------------- launch ----------------
extern "C" void kernel_launch(void* const* d_in, const int* in_sizes, int n_in,
                              void* d_out, int out_size) {
    const float* hidden = (const float*)d_in[0];
    const int* amask = (const int*)d_in[1];
    const int* pos = (const int*)d_in[2];
    const float* wq = (const float*)d_in[3];
    const float* wk = (const float*)d_in[4];
    const float* wv = (const float*)d_in[5];
    const float* wo = (const float*)d_in[6];
    const float* w_gate = (const float*)d_in[7];
    const float* w_up = (const float*)d_in[8];
    const float* w_down = (const float*)d_in[9];
    const float* ln1 = (const float*)d_in[10];
    const float* ln2 = (const float*)d_in[11];
    const float* apw = (const float*)d_in[12];
    const float* apb = (const float*)d_in[13];
    const float* mpw = (const float*)d_in[14];
    const float* mpb = (const float*)d_in[15];
    float* out = (float*)d_out;

    float *hs, *q, *k, *v, *attn, *res2, *hlog, *hmask, *mlog, *fcm, *gate, *up;
    cudaGetSymbolAddress((void**)&hs, g_hs);
    cudaGetSymbolAddress((void**)&q, g_q);
    cudaGetSymbolAddress((void**)&k, g_k);
    cudaGetSymbolAddress((void**)&v, g_v);
    cudaGetSymbolAddress((void**)&attn, g_attn);
    cudaGetSymbolAddress((void**)&res2, g_res2);
    cudaGetSymbolAddress((void**)&hlog, g_hlogit);
    cudaGetSymbolAddress((void**)&hmask, g_headmask);
    cudaGetSymbolAddress((void**)&mlog, g_mlogit);
    cudaGetSymbolAddress((void**)&fcm, g_fcmask);
    cudaGetSymbolAddress((void**)&gate, g_gate);
    cudaGetSymbolAddress((void**)&up, g_up);

    const int SMEM_B = 8 * HBUF * (int)sizeof(__nv_bfloat16);   // 81920 B
    cudaFuncSetAttribute(bf16x3gemm_nt,
                         cudaFuncAttributeMaxDynamicSharedMemorySize, SMEM_B);

    dim3 gHH(HH / 128, TT / 128);
    dim3 gII(II / 128, TT / 128);

    rmsnorm_kernel<<<TT, 256>>>(hidden, ln1, hs);
    // selection-critical + residual-stream GEMMs: exact fp32 FFMA
    sgemm_nt_kernel<<<gHH, 256>>>(hs, wq, nullptr, nullptr, q, TT, HH, HH);
    sgemm_nt_kernel<<<gHH, 256>>>(hs, wk, nullptr, nullptr, k, TT, HH, HH);
    sgemm_nt_kernel<<<gHH, 256>>>(hs, wv, nullptr, nullptr, v, TT, HH, HH);
    rope_kernel<<<(TT * NH * 64 + 255) / 256, 256>>>(q, k, pos);
    attn_pred_kernel<<<TT, 256>>>(hs, apw, apb, hlog);
    head_mask_kernel<<<TT, 32>>>(hlog, hmask);
    attention_kernel<<<dim3(TT, NH), 128>>>(q, k, v, hmask, amask, attn);
    sgemm_nt_kernel<<<gHH, 256>>>(attn, wo, nullptr, hidden, res2, TT, HH, HH);
    rmsnorm_kernel<<<TT, 256>>>(res2, ln2, hs);
    sgemm_nt_kernel<<<gII, 256>>>(hs, mpw, mpb, nullptr, mlog, TT, II, HH);
    mlp_topk_kernel<<<TT, 256>>>(mlog, fcm);
    // direct-output GEMMs (downstream of all top-k): bf16x3 tensor path
    bf16x3gemm_nt<<<gII, 256, SMEM_B>>>(hs, w_gate, nullptr, nullptr, gate, TT, II, HH);
    bf16x3gemm_nt<<<gII, 256, SMEM_B>>>(hs, w_up, nullptr, nullptr, up, TT, II, HH);
    silu_mul_mask_kernel<<<(TT * II + 255) / 256, 256>>>(gate, up, fcm, TT * II);
    bf16x3gemm_nt<<<gHH, 256, SMEM_B>>>(gate, w_down, nullptr, res2, out, TT, HH, II);
}

// round 10
// speedup vs baseline: 2.1711x; 1.4229x over previous
#include <cuda_runtime.h>
#include <cuda_bf16.h>
#include <math.h>
#include <stdint.h>

#define TT 2048
#define HH 4096
#define NH 32
#define HD 128
#define II 11008
#define ATTN_TOPK 16
#define MLP_TOPK 2048
#define QB 8

// ---------------- scratch ----------------
__device__ float g_hs[TT * HH];
__device__ float g_q[TT * HH];
__device__ float g_k[TT * HH];
__device__ float g_v[TT * HH];
__device__ float g_attn[TT * HH];
__device__ float g_res2[TT * HH];
__device__ float g_hlogit[TT * NH];
__device__ float g_headmask[TT * NH];
__device__ float g_mlogit[TT * II];
__device__ float g_fcmask[TT * II];
__device__ float g_gate[TT * II];
__device__ float g_up[TT * II];
__device__ float g_thr[TT];

// ---------------- RMSNorm ----------------
__global__ void rmsnorm_kernel(const float* __restrict__ x,
                               const float* __restrict__ w,
                               float* __restrict__ out) {
    int row = blockIdx.x;
    const float4* x4 = (const float4*)(x + (size_t)row * HH);
    const float4* w4 = (const float4*)w;
    float s = 0.f;
    for (int i = threadIdx.x; i < HH / 4; i += 256) {
        float4 v = x4[i];
        s += v.x * v.x + v.y * v.y + v.z * v.z + v.w * v.w;
    }
    __shared__ float red[256];
    red[threadIdx.x] = s;
    __syncthreads();
    for (int o = 128; o > 0; o >>= 1) {
        if (threadIdx.x < o) red[threadIdx.x] += red[threadIdx.x + o];
        __syncthreads();
    }
    float rs = rsqrtf(red[0] / (float)HH + 1e-6f);
    float4* o4 = (float4*)(out + (size_t)row * HH);
    for (int i = threadIdx.x; i < HH / 4; i += 256) {
        float4 a = x4[i];
        float4 ww = w4[i];
        a.x = a.x * rs * ww.x;
        a.y = a.y * rs * ww.y;
        a.z = a.z * rs * ww.z;
        a.w = a.w * rs * ww.w;
        o4[i] = a;
    }
}

// ---------------- exact fp32 SGEMM (proven R2 config) ----------------------
__global__ void __launch_bounds__(256) sgemm_nt_kernel(
    const float* __restrict__ A, const float* __restrict__ B,
    const float* __restrict__ bias, const float* __restrict__ addsrc,
    float* __restrict__ C, int M, int N, int K) {
    __shared__ float As[16][132];
    __shared__ float Bs[16][132];
    const int bm = blockIdx.y * 128;
    const int bn = blockIdx.x * 128;
    const int tid = threadIdx.x;
    const int tr = tid >> 4;
    const int tc = tid & 15;

    float acc[8][8];
#pragma unroll
    for (int i = 0; i < 8; i++)
#pragma unroll
        for (int j = 0; j < 8; j++) acc[i][j] = 0.f;

    const int lr = tid >> 2;
    const int lc = (tid & 3) * 4;
    const float* Aptr = A + (size_t)(bm + lr) * K + lc;
    const float* Bptr = B + (size_t)(bn + lr) * K + lc;
    const size_t rowoff = (size_t)64 * K;

    for (int k0 = 0; k0 < K; k0 += 16) {
        float4 a0 = *(const float4*)(Aptr + k0);
        float4 a1 = *(const float4*)(Aptr + k0 + rowoff);
        float4 b0 = *(const float4*)(Bptr + k0);
        float4 b1 = *(const float4*)(Bptr + k0 + rowoff);
        As[lc + 0][lr] = a0.x; As[lc + 1][lr] = a0.y;
        As[lc + 2][lr] = a0.z; As[lc + 3][lr] = a0.w;
        As[lc + 0][lr + 64] = a1.x; As[lc + 1][lr + 64] = a1.y;
        As[lc + 2][lr + 64] = a1.z; As[lc + 3][lr + 64] = a1.w;
        Bs[lc + 0][lr] = b0.x; Bs[lc + 1][lr] = b0.y;
        Bs[lc + 2][lr] = b0.z; Bs[lc + 3][lr] = b0.w;
        Bs[lc + 0][lr + 64] = b1.x; Bs[lc + 1][lr + 64] = b1.y;
        Bs[lc + 2][lr + 64] = b1.z; Bs[lc + 3][lr + 64] = b1.w;
        __syncthreads();
#pragma unroll
        for (int kk = 0; kk < 16; kk++) {
            float ra[8], rb[8];
#pragma unroll
            for (int i = 0; i < 8; i++) ra[i] = As[kk][tr * 8 + i];
#pragma unroll
            for (int j = 0; j < 8; j++) rb[j] = Bs[kk][tc * 8 + j];
#pragma unroll
            for (int i = 0; i < 8; i++)
#pragma unroll
                for (int j = 0; j < 8; j++)
                    acc[i][j] = fmaf(ra[i], rb[j], acc[i][j]);
        }
        __syncthreads();
    }

#pragma unroll
    for (int i = 0; i < 8; i++) {
        int row = bm + tr * 8 + i;
        size_t base = (size_t)row * N + bn + tc * 8;
#pragma unroll
        for (int j = 0; j < 8; j += 4) {
            float4 r;
            r.x = acc[i][j + 0]; r.y = acc[i][j + 1];
            r.z = acc[i][j + 2]; r.w = acc[i][j + 3];
            if (bias) {
                int cn = bn + tc * 8 + j;
                r.x += bias[cn + 0]; r.y += bias[cn + 1];
                r.z += bias[cn + 2]; r.w += bias[cn + 3];
            }
            if (addsrc) {
                float4 s = *(const float4*)(addsrc + base + j);
                r.x += s.x; r.y += s.y; r.z += s.z; r.w += s.w;
            }
            *(float4*)(C + base + j) = r;
        }
    }
}

// ================= bf16x3 mma GEMM =========================================
__device__ __forceinline__ uint32_t packbf(__nv_bfloat16 a, __nv_bfloat16 b) {
    __nv_bfloat162 t;
    t.x = a; t.y = b;
    return *(uint32_t*)&t;
}

__device__ __forceinline__ void split4(float4 v, uint2& hi, uint2& lo) {
    __nv_bfloat16 hx = __float2bfloat16(v.x);
    __nv_bfloat16 hy = __float2bfloat16(v.y);
    __nv_bfloat16 hz = __float2bfloat16(v.z);
    __nv_bfloat16 hw = __float2bfloat16(v.w);
    __nv_bfloat16 lx = __float2bfloat16(v.x - __bfloat162float(hx));
    __nv_bfloat16 ly = __float2bfloat16(v.y - __bfloat162float(hy));
    __nv_bfloat16 lz = __float2bfloat16(v.z - __bfloat162float(hz));
    __nv_bfloat16 lw = __float2bfloat16(v.w - __bfloat162float(hw));
    hi.x = packbf(hx, hy); hi.y = packbf(hz, hw);
    lo.x = packbf(lx, ly); lo.y = packbf(lz, lw);
}

__device__ __forceinline__ void mma16(float* c, uint32_t a0, uint32_t a1,
                                      uint32_t a2, uint32_t a3,
                                      uint32_t b0, uint32_t b1) {
    asm volatile(
        "mma.sync.aligned.m16n8k16.row.col.f32.bf16.bf16.f32 "
        "{%0,%1,%2,%3}, {%4,%5,%6,%7}, {%8,%9}, {%0,%1,%2,%3};"
        : "+f"(c[0]), "+f"(c[1]), "+f"(c[2]), "+f"(c[3])
        : "r"(a0), "r"(a1), "r"(a2), "r"(a3), "r"(b0), "r"(b1));
}

#define STRH 40
#define HBUF (128 * STRH)

__global__ void __launch_bounds__(256) bf16x3gemm_nt(
    const float* __restrict__ A, const float* __restrict__ B,
    const float* __restrict__ bias, const float* __restrict__ addsrc,
    float* __restrict__ C, int M, int N, int K) {
    extern __shared__ __nv_bfloat16 sh[];
    __nv_bfloat16* Ah = sh;
    __nv_bfloat16* Al = sh + 2 * HBUF;
    __nv_bfloat16* Bh = sh + 4 * HBUF;
    __nv_bfloat16* Bl = sh + 6 * HBUF;

    const int tid = threadIdx.x;
    const int lane = tid & 31;
    const int warp = tid >> 5;
    const int wm = warp & 1;
    const int wn = warp >> 1;
    const int g = lane >> 2;
    const int tg = lane & 3;
    const int bm = blockIdx.y * 128;
    const int bn = blockIdx.x * 128;

    float acc[4][4][4];
#pragma unroll
    for (int i = 0; i < 4; i++)
#pragma unroll
        for (int j = 0; j < 4; j++)
#pragma unroll
            for (int l = 0; l < 4; l++) acc[i][j][l] = 0.f;

    const int lrow = tid >> 3;
    const int lc4 = (tid & 7) * 4;
    const float* Ag = A + (size_t)(bm + lrow) * K + lc4;
    const float* Bg = B + (size_t)(bn + lrow) * K + lc4;

    float4 pa[4], pb[4];
#pragma unroll
    for (int p = 0; p < 4; p++) {
        pa[p] = *(const float4*)(Ag + (size_t)(p * 32) * K);
        pb[p] = *(const float4*)(Bg + (size_t)(p * 32) * K);
    }

    const int NKT = K / 32;

#pragma unroll
    for (int p = 0; p < 4; p++) {
        int row = lrow + p * 32;
        uint2 hi, lo;
        split4(pa[p], hi, lo);
        *(uint2*)(Ah + row * STRH + lc4) = hi;
        *(uint2*)(Al + row * STRH + lc4) = lo;
        split4(pb[p], hi, lo);
        *(uint2*)(Bh + row * STRH + lc4) = hi;
        *(uint2*)(Bl + row * STRH + lc4) = lo;
    }
    __syncthreads();

    for (int kt = 0; kt < NKT; kt++) {
        const int cur = kt & 1;
        const bool more = (kt + 1 < NKT);
        if (more) {
            size_t off = (size_t)(kt + 1) * 32;
#pragma unroll
            for (int p = 0; p < 4; p++) {
                pa[p] = *(const float4*)(Ag + (size_t)(p * 32) * K + off);
                pb[p] = *(const float4*)(Bg + (size_t)(p * 32) * K + off);
            }
        }
        const __nv_bfloat16* Ach = Ah + cur * HBUF;
        const __nv_bfloat16* Acl = Al + cur * HBUF;
        const __nv_bfloat16* Bch = Bh + cur * HBUF;
        const __nv_bfloat16* Bcl = Bl + cur * HBUF;

#pragma unroll
        for (int ks = 0; ks < 2; ks++) {
            const int k = ks * 16;
            uint32_t afh[4][4], afl[4][4], bfh[4][2], bfl[4][2];
#pragma unroll
            for (int mi = 0; mi < 4; mi++) {
                int rb = wm * 64 + mi * 16;
                int i00 = (rb + g) * STRH + k + 2 * tg;
                int i01 = (rb + 8 + g) * STRH + k + 2 * tg;
                afh[mi][0] = *(const uint32_t*)(Ach + i00);
                afh[mi][1] = *(const uint32_t*)(Ach + i01);
                afh[mi][2] = *(const uint32_t*)(Ach + i00 + 8);
                afh[mi][3] = *(const uint32_t*)(Ach + i01 + 8);
                afl[mi][0] = *(const uint32_t*)(Acl + i00);
                afl[mi][1] = *(const uint32_t*)(Acl + i01);
                afl[mi][2] = *(const uint32_t*)(Acl + i00 + 8);
                afl[mi][3] = *(const uint32_t*)(Acl + i01 + 8);
            }
#pragma unroll
            for (int ni = 0; ni < 4; ni++) {
                int nb = wn * 32 + ni * 8;
                int j0 = (nb + g) * STRH + k + 2 * tg;
                bfh[ni][0] = *(const uint32_t*)(Bch + j0);
                bfh[ni][1] = *(const uint32_t*)(Bch + j0 + 8);
                bfl[ni][0] = *(const uint32_t*)(Bcl + j0);
                bfl[ni][1] = *(const uint32_t*)(Bcl + j0 + 8);
            }
#pragma unroll
            for (int mi = 0; mi < 4; mi++)
#pragma unroll
                for (int ni = 0; ni < 4; ni++) {
                    mma16(acc[mi][ni], afh[mi][0], afh[mi][1], afh[mi][2],
                          afh[mi][3], bfh[ni][0], bfh[ni][1]);
                    mma16(acc[mi][ni], afh[mi][0], afh[mi][1], afh[mi][2],
                          afh[mi][3], bfl[ni][0], bfl[ni][1]);
                    mma16(acc[mi][ni], afl[mi][0], afl[mi][1], afl[mi][2],
                          afl[mi][3], bfh[ni][0], bfh[ni][1]);
                }
        }

        if (more) {
            const int nxt = (kt + 1) & 1;
            __nv_bfloat16* Adh = Ah + nxt * HBUF;
            __nv_bfloat16* Adl = Al + nxt * HBUF;
            __nv_bfloat16* Bdh = Bh + nxt * HBUF;
            __nv_bfloat16* Bdl = Bl + nxt * HBUF;
#pragma unroll
            for (int p = 0; p < 4; p++) {
                int row = lrow + p * 32;
                uint2 hi, lo;
                split4(pa[p], hi, lo);
                *(uint2*)(Adh + row * STRH + lc4) = hi;
                *(uint2*)(Adl + row * STRH + lc4) = lo;
                split4(pb[p], hi, lo);
                *(uint2*)(Bdh + row * STRH + lc4) = hi;
                *(uint2*)(Bdl + row * STRH + lc4) = lo;
            }
        }
        __syncthreads();
    }

#pragma unroll
    for (int mi = 0; mi < 4; mi++) {
        int r0 = bm + wm * 64 + mi * 16 + g;
#pragma unroll
        for (int ni = 0; ni < 4; ni++) {
            int col = bn + wn * 32 + ni * 8 + tg * 2;
            float2 v0, v1;
            v0.x = acc[mi][ni][0]; v0.y = acc[mi][ni][1];
            v1.x = acc[mi][ni][2]; v1.y = acc[mi][ni][3];
            if (bias) {
                float2 bb = *(const float2*)(bias + col);
                v0.x += bb.x; v0.y += bb.y;
                v1.x += bb.x; v1.y += bb.y;
            }
            size_t i0 = (size_t)r0 * N + col;
            size_t i1 = (size_t)(r0 + 8) * N + col;
            if (addsrc) {
                float2 s0 = *(const float2*)(addsrc + i0);
                float2 s1 = *(const float2*)(addsrc + i1);
                v0.x += s0.x; v0.y += s0.y;
                v1.x += s1.x; v1.y += s1.y;
            }
            *(float2*)(C + i0) = v0;
            *(float2*)(C + i1) = v1;
        }
    }
}

// ---------------- RoPE (position_ids int32) ----------------
__global__ void rope_kernel(float* __restrict__ q, float* __restrict__ k,
                            const int* __restrict__ pos) {
    int idx = blockIdx.x * 256 + threadIdx.x;
    if (idx >= TT * NH * 64) return;
    int j = idx & 63;
    int th = idx >> 6;
    int t = th >> 5;
    float p = (float)pos[t];
    float ang = p * exp2f(-(float)j * (13.287712379549449f / 64.f));
    float s, c;
    sincosf(ang, &s, &c);
    size_t base = (size_t)th * HD + j;
    float q0 = q[base], q1 = q[base + 64];
    q[base] = q0 * c - q1 * s;
    q[base + 64] = q1 * c + q0 * s;
    float k0 = k[base], k1 = k[base + 64];
    k[base] = k0 * c - k1 * s;
    k[base + 64] = k1 * c + k0 * s;
}

// ---------------- attn predictor logits ----------------
__global__ void attn_pred_kernel(const float* __restrict__ hs,
                                 const float* __restrict__ w,
                                 const float* __restrict__ b,
                                 float* __restrict__ out) {
    int t = blockIdx.x;
    int warp = threadIdx.x >> 5, lane = threadIdx.x & 31;
    const float* hsrow = hs + (size_t)t * HH;
    for (int hh = 0; hh < 4; hh++) {
        int h = warp * 4 + hh;
        const float* wr = w + (size_t)h * HH;
        float s = 0.f;
        for (int kk = lane; kk < HH; kk += 32) s += hsrow[kk] * wr[kk];
        for (int o = 16; o > 0; o >>= 1) s += __shfl_xor_sync(0xffffffffu, s, o);
        if (lane == 0) out[t * NH + h] = s + b[h];
    }
}

// ---------------- head top-16 mask ----------------
__global__ void head_mask_kernel(const float* __restrict__ logit,
                                 float* __restrict__ mask) {
    int t = blockIdx.x;
    int h = threadIdx.x;
    float v = logit[t * NH + h];
    int rank = 0;
    for (int j = 0; j < NH; j++) {
        float vj = logit[t * NH + j];
        rank += (vj > v) || (vj == v && j < h);
    }
    mask[t * NH + h] = (rank < ATTN_TOPK) ? 1.f : 0.f;
}

// ---------------- attention: 8 q-rows per block, two-pass softmax ----------
// dynamic smem: qs[QB*HD] then P[TT][QB] (float4-packed pairs)
__global__ void __launch_bounds__(128)
attention8_kernel(const float* __restrict__ q, const float* __restrict__ k,
                  const float* __restrict__ v, const float* __restrict__ hmask,
                  const int* __restrict__ amask, float* __restrict__ out) {
    extern __shared__ float asm_[];
    float* qs = asm_;                 // QB*HD
    float* P = asm_ + QB * HD;        // TT*QB
    __shared__ float red[128];
    const int t0 = blockIdx.x * QB;
    const int h = blockIdx.y;
    const int tid = threadIdx.x;
    const float NEGF = -3.4e38f;

    float act[QB];
    bool anyact = false;
#pragma unroll
    for (int r = 0; r < QB; r++) {
        act[r] = hmask[(t0 + r) * NH + h];
        anyact |= (act[r] != 0.f);
    }
    if (!anyact) {
#pragma unroll
        for (int r = 0; r < QB; r++)
            out[(size_t)(t0 + r) * HH + h * HD + tid] = 0.f;
        return;
    }
#pragma unroll
    for (int r = 0; r < QB; r++)
        qs[r * HD + tid] = q[(size_t)(t0 + r) * HH + h * HD + tid] *
                           0.08838834764831845f;
    __syncthreads();

    const int nk = t0 + QB;
    float lm[QB];
#pragma unroll
    for (int r = 0; r < QB; r++) lm[r] = NEGF;

    // pass1: scores
    for (int j = tid; j < nk; j += 128) {
        float s[QB];
#pragma unroll
        for (int r = 0; r < QB; r++) s[r] = 0.f;
        bool am = (amask[j] != 0);
        if (am) {
            const float4* kr = (const float4*)(k + (size_t)j * HH + h * HD);
#pragma unroll
            for (int d4 = 0; d4 < 32; d4++) {
                float4 kv = kr[d4];
#pragma unroll
                for (int r = 0; r < QB; r++) {
                    float4 qv = *(const float4*)(qs + r * HD + d4 * 4);
                    s[r] += qv.x * kv.x + qv.y * kv.y + qv.z * kv.z +
                            qv.w * kv.w;
                }
            }
        }
        float val[QB];
#pragma unroll
        for (int r = 0; r < QB; r++) {
            val[r] = (am && j <= t0 + r) ? s[r] : NEGF;
            lm[r] = fmaxf(lm[r], val[r]);
        }
        float4 o0, o1;
        o0.x = val[0]; o0.y = val[1]; o0.z = val[2]; o0.w = val[3];
        o1.x = val[4]; o1.y = val[5]; o1.z = val[6]; o1.w = val[7];
        ((float4*)(P + j * QB))[0] = o0;
        ((float4*)(P + j * QB))[1] = o1;
    }
    // row maxes
    float M[QB];
#pragma unroll
    for (int r = 0; r < QB; r++) {
        red[tid] = lm[r];
        __syncthreads();
        for (int o = 64; o > 0; o >>= 1) {
            if (tid < o) red[tid] = fmaxf(red[tid], red[tid + o]);
            __syncthreads();
        }
        M[r] = red[0];
        __syncthreads();
    }
    // pass2: exp + sums
    float ls[QB];
#pragma unroll
    for (int r = 0; r < QB; r++) ls[r] = 0.f;
    for (int j = tid; j < nk; j += 128) {
        float4 a = ((float4*)(P + j * QB))[0];
        float4 b = ((float4*)(P + j * QB))[1];
        a.x = __expf(a.x - M[0]); a.y = __expf(a.y - M[1]);
        a.z = __expf(a.z - M[2]); a.w = __expf(a.w - M[3]);
        b.x = __expf(b.x - M[4]); b.y = __expf(b.y - M[5]);
        b.z = __expf(b.z - M[6]); b.w = __expf(b.w - M[7]);
        ls[0] += a.x; ls[1] += a.y; ls[2] += a.z; ls[3] += a.w;
        ls[4] += b.x; ls[5] += b.y; ls[6] += b.z; ls[7] += b.w;
        ((float4*)(P + j * QB))[0] = a;
        ((float4*)(P + j * QB))[1] = b;
    }
    float inv[QB];
#pragma unroll
    for (int r = 0; r < QB; r++) {
        red[tid] = ls[r];
        __syncthreads();
        for (int o = 64; o > 0; o >>= 1) {
            if (tid < o) red[tid] += red[tid + o];
            __syncthreads();
        }
        inv[r] = 1.f / red[0];
        __syncthreads();
    }
    // pass3: PV (thread owns column tid)
    float acc[QB];
#pragma unroll
    for (int r = 0; r < QB; r++) acc[r] = 0.f;
#pragma unroll 4
    for (int j = 0; j < nk; j++) {
        float vv = v[(size_t)j * HH + h * HD + tid];
        float4 a = ((float4*)(P + j * QB))[0];
        float4 b = ((float4*)(P + j * QB))[1];
        acc[0] = fmaf(a.x, vv, acc[0]); acc[1] = fmaf(a.y, vv, acc[1]);
        acc[2] = fmaf(a.z, vv, acc[2]); acc[3] = fmaf(a.w, vv, acc[3]);
        acc[4] = fmaf(b.x, vv, acc[4]); acc[5] = fmaf(b.y, vv, acc[5]);
        acc[6] = fmaf(b.z, vv, acc[6]); acc[7] = fmaf(b.w, vv, acc[7]);
    }
#pragma unroll
    for (int r = 0; r < QB; r++)
        out[(size_t)(t0 + r) * HH + h * HD + tid] =
            (act[r] != 0.f) ? acc[r] * inv[r] : 0.f;
}

// ---------------- top-k radix select machinery ----------------
__device__ __forceinline__ unsigned fkey(float x) {
    unsigned b = __float_as_uint(x);
    return (b & 0x80000000u) ? ~b : (b | 0x80000000u);
}
__device__ __forceinline__ float unfkey(unsigned k) {
    unsigned b = (k & 0x80000000u) ? (k & 0x7fffffffu) : ~k;
    return __uint_as_float(b);
}

// threshold-only radix select (2048th largest value per row)
__global__ void mlp_thresh_kernel(const float* __restrict__ logits,
                                  float* __restrict__ thr) {
    int row = blockIdx.x;
    const float* lr = logits + (size_t)row * II;
    __shared__ unsigned hist[256];
    __shared__ unsigned sh_sel, sh_kk;
    int tid = threadIdx.x;
    unsigned prefix = 0;
    unsigned kk = MLP_TOPK;
    for (int shift = 24; shift >= 0; shift -= 8) {
        hist[tid] = 0;
        __syncthreads();
        for (int i = tid; i < II; i += 256) {
            unsigned u = fkey(lr[i]);
            bool ok = (shift == 24) || ((u >> (shift + 8)) == prefix);
            if (ok) atomicAdd(&hist[(u >> shift) & 255u], 1u);
        }
        __syncthreads();
        if (tid == 0) {
            unsigned c = 0;
            int sel = 0;
            for (int b = 255; b >= 0; b--) {
                c += hist[b];
                if (c >= kk) { sel = b; break; }
            }
            sh_sel = (unsigned)sel;
            sh_kk = kk - (c - hist[sel]);
        }
        __syncthreads();
        prefix = (prefix << 8) | sh_sel;
        kk = sh_kk;
        __syncthreads();
    }
    if (tid == 0) thr[row] = unfkey(prefix);
}

// exact FFMA recompute of logits within +-BAND of the noisy threshold
#define BAND 4e-3f
__global__ void mlp_correct_kernel(float* __restrict__ mlog,
                                   const float* __restrict__ hs,
                                   const float* __restrict__ w,
                                   const float* __restrict__ b,
                                   const float* __restrict__ thr) {
    int row = blockIdx.x;
    int tid = threadIdx.x;
    __shared__ int cnt;
    __shared__ int idxs[1024];
    if (tid == 0) cnt = 0;
    __syncthreads();
    float th = thr[row];
    float* lr = mlog + (size_t)row * II;
    for (int i = tid; i < II; i += 256) {
        if (fabsf(lr[i] - th) <= BAND) {
            int p = atomicAdd(&cnt, 1);
            if (p < 1024) idxs[p] = i;
        }
    }
    __syncthreads();
    int n = cnt < 1024 ? cnt : 1024;
    int warp = tid >> 5, lane = tid & 31;
    const float* hsr = hs + (size_t)row * HH;
    for (int c = warp; c < n; c += 8) {
        int i = idxs[c];
        const float* wr = w + (size_t)i * HH;
        float s = 0.f;
        for (int kk = lane; kk < HH; kk += 32) s += hsr[kk] * wr[kk];
        for (int o = 16; o > 0; o >>= 1) s += __shfl_xor_sync(0xffffffffu, s, o);
        if (lane == 0) lr[i] = s + b[i];
    }
}

// final exact top-2048 mask (jax tie semantics)
__global__ void mlp_topk_kernel(const float* __restrict__ logits,
                                float* __restrict__ mask) {
    int row = blockIdx.x;
    const float* lr = logits + (size_t)row * II;
    __shared__ unsigned hist[256];
    __shared__ unsigned sh_sel, sh_kk;
    __shared__ unsigned sh_cnt[2];
    int tid = threadIdx.x;
    unsigned prefix = 0;
    unsigned kk = MLP_TOPK;
    for (int shift = 24; shift >= 0; shift -= 8) {
        hist[tid] = 0;
        __syncthreads();
        for (int i = tid; i < II; i += 256) {
            unsigned u = fkey(lr[i]);
            bool ok = (shift == 24) || ((u >> (shift + 8)) == prefix);
            if (ok) atomicAdd(&hist[(u >> shift) & 255u], 1u);
        }
        __syncthreads();
        if (tid == 0) {
            unsigned c = 0;
            int sel = 0;
            for (int b = 255; b >= 0; b--) {
                c += hist[b];
                if (c >= kk) { sel = b; break; }
            }
            sh_sel = (unsigned)sel;
            sh_kk = kk - (c - hist[sel]);
        }
        __syncthreads();
        prefix = (prefix << 8) | sh_sel;
        kk = sh_kk;
        __syncthreads();
    }
    unsigned thresh = prefix;
    if (tid < 2) sh_cnt[tid] = 0;
    __syncthreads();
    unsigned lg = 0, le = 0;
    for (int i = tid; i < II; i += 256) {
        unsigned u = fkey(lr[i]);
        if (u > thresh) lg++;
        else if (u == thresh) le++;
    }
    atomicAdd(&sh_cnt[0], lg);
    atomicAdd(&sh_cnt[1], le);
    __syncthreads();
    unsigned g = sh_cnt[0], e = sh_cnt[1];
    float* mr = mask + (size_t)row * II;
    if (g + e == MLP_TOPK) {
        for (int i = tid; i < II; i += 256)
            mr[i] = (fkey(lr[i]) >= thresh) ? 1.f : 0.f;
    } else {
        for (int i = tid; i < II; i += 256)
            mr[i] = (fkey(lr[i]) > thresh) ? 1.f : 0.f;
        __syncthreads();
        if (tid == 0) {
            unsigned quota = MLP_TOPK - g;
            for (int i = 0; i < II && quota > 0; i++) {
                if (fkey(lr[i]) == thresh) { mr[i] = 1.f; quota--; }
            }
        }
    }
}

// ---------------- silu * up * mask ----------------
__global__ void silu_mul_mask_kernel(float* __restrict__ gate,
                                     const float* __restrict__ up,
                                     const float* __restrict__ mask, int n) {
    int i = blockIdx.x * 256 + threadIdx.x;
    if (i < n) {
        float x = gate[i];
        float si = x / (1.f + __expf(-x));
        gate[i] = si * up[i] * mask[i];
    }
}

// ---------------- launch ----------------
extern "C" void kernel_launch(void* const* d_in, const int* in_sizes, int n_in,
                              void* d_out, int out_size) {
    const float* hidden = (const float*)d_in[0];
    const int* amask = (const int*)d_in[1];
    const int* pos = (const int*)d_in[2];
    const float* wq = (const float*)d_in[3];
    const float* wk = (const float*)d_in[4];
    const float* wv = (const float*)d_in[5];
    const float* wo = (const float*)d_in[6];
    const float* w_gate = (const float*)d_in[7];
    const float* w_up = (const float*)d_in[8];
    const float* w_down = (const float*)d_in[9];
    const float* ln1 = (const float*)d_in[10];
    const float* ln2 = (const float*)d_in[11];
    const float* apw = (const float*)d_in[12];
    const float* apb = (const float*)d_in[13];
    const float* mpw = (const float*)d_in[14];
    const float* mpb = (const float*)d_in[15];
    float* out = (float*)d_out;

    float *hs, *q, *k, *v, *attn, *res2, *hlog, *hmask, *mlog, *fcm, *gate, *up,
        *thr;
    cudaGetSymbolAddress((void**)&hs, g_hs);
    cudaGetSymbolAddress((void**)&q, g_q);
    cudaGetSymbolAddress((void**)&k, g_k);
    cudaGetSymbolAddress((void**)&v, g_v);
    cudaGetSymbolAddress((void**)&attn, g_attn);
    cudaGetSymbolAddress((void**)&res2, g_res2);
    cudaGetSymbolAddress((void**)&hlog, g_hlogit);
    cudaGetSymbolAddress((void**)&hmask, g_headmask);
    cudaGetSymbolAddress((void**)&mlog, g_mlogit);
    cudaGetSymbolAddress((void**)&fcm, g_fcmask);
    cudaGetSymbolAddress((void**)&gate, g_gate);
    cudaGetSymbolAddress((void**)&up, g_up);
    cudaGetSymbolAddress((void**)&thr, g_thr);

    const int SMEM_B = 8 * HBUF * (int)sizeof(__nv_bfloat16);   // 81920 B
    cudaFuncSetAttribute(bf16x3gemm_nt,
                         cudaFuncAttributeMaxDynamicSharedMemorySize, SMEM_B);
    const int SMEM_A = (QB * HD + TT * QB) * (int)sizeof(float);  // 69632 B
    cudaFuncSetAttribute(attention8_kernel,
                         cudaFuncAttributeMaxDynamicSharedMemorySize, SMEM_A);

    dim3 gHH(HH / 128, TT / 128);
    dim3 gII(II / 128, TT / 128);

    rmsnorm_kernel<<<TT, 256>>>(hidden, ln1, hs);
    // selection-critical GEMMs: exact fp32 FFMA
    sgemm_nt_kernel<<<gHH, 256>>>(hs, wq, nullptr, nullptr, q, TT, HH, HH);
    sgemm_nt_kernel<<<gHH, 256>>>(hs, wk, nullptr, nullptr, k, TT, HH, HH);
    sgemm_nt_kernel<<<gHH, 256>>>(hs, wv, nullptr, nullptr, v, TT, HH, HH);
    rope_kernel<<<(TT * NH * 64 + 255) / 256, 256>>>(q, k, pos);
    attn_pred_kernel<<<TT, 256>>>(hs, apw, apb, hlog);
    head_mask_kernel<<<TT, 32>>>(hlog, hmask);
    attention8_kernel<<<dim3(TT / QB, NH), 128, SMEM_A>>>(q, k, v, hmask, amask,
                                                          attn);
    sgemm_nt_kernel<<<gHH, 256>>>(attn, wo, nullptr, hidden, res2, TT, HH, HH);
    rmsnorm_kernel<<<TT, 256>>>(res2, ln2, hs);
    // mlogit: fast bf16x3 + exact band repair -> selection is fp32-exact
    bf16x3gemm_nt<<<gII, 256, SMEM_B>>>(hs, mpw, mpb, nullptr, mlog, TT, II, HH);
    mlp_thresh_kernel<<<TT, 256>>>(mlog, thr);
    mlp_correct_kernel<<<TT, 256>>>(mlog, hs, mpw, mpb, thr);
    mlp_topk_kernel<<<TT, 256>>>(mlog, fcm);
    // direct-output GEMMs: bf16x3 tensor path
    bf16x3gemm_nt<<<gII, 256, SMEM_B>>>(hs, w_gate, nullptr, nullptr, gate, TT, II, HH);
    bf16x3gemm_nt<<<gII, 256, SMEM_B>>>(hs, w_up, nullptr, nullptr, up, TT, II, HH);
    silu_mul_mask_kernel<<<(TT * II + 255) / 256, 256>>>(gate, up, fcm, TT * II);
    bf16x3gemm_nt<<<gHH, 256, SMEM_B>>>(gate, w_down, nullptr, res2, out, TT, HH, II);
}

// round 11
// speedup vs baseline: 2.7833x; 1.2820x over previous
#include <cuda_runtime.h>
#include <cuda_bf16.h>
#include <math.h>
#include <stdint.h>

#define TT 2048
#define HH 4096
#define NH 32
#define HD 128
#define II 11008
#define ATTN_TOPK 16
#define MLP_TOPK 2048
#define QB 8

// ---------------- scratch ----------------
__device__ float g_hs[TT * HH];
__device__ float g_q[TT * HH];
__device__ float g_k[TT * HH];
__device__ float g_v[TT * HH];
__device__ float g_attn[TT * HH];
__device__ float g_res2[TT * HH];
__device__ float g_hlogit[TT * NH];
__device__ float g_headmask[TT * NH];
__device__ float g_mlogit[TT * II];
__device__ float g_fcmask[TT * II];
__device__ float g_gate[TT * II];
__device__ float g_up[TT * II];
__device__ float g_thr[TT];

// ---------------- RMSNorm ----------------
__global__ void rmsnorm_kernel(const float* __restrict__ x,
                               const float* __restrict__ w,
                               float* __restrict__ out) {
    int row = blockIdx.x;
    const float4* x4 = (const float4*)(x + (size_t)row * HH);
    const float4* w4 = (const float4*)w;
    float s = 0.f;
    for (int i = threadIdx.x; i < HH / 4; i += 256) {
        float4 v = x4[i];
        s += v.x * v.x + v.y * v.y + v.z * v.z + v.w * v.w;
    }
    __shared__ float red[256];
    red[threadIdx.x] = s;
    __syncthreads();
    for (int o = 128; o > 0; o >>= 1) {
        if (threadIdx.x < o) red[threadIdx.x] += red[threadIdx.x + o];
        __syncthreads();
    }
    float rs = rsqrtf(red[0] / (float)HH + 1e-6f);
    float4* o4 = (float4*)(out + (size_t)row * HH);
    for (int i = threadIdx.x; i < HH / 4; i += 256) {
        float4 a = x4[i];
        float4 ww = w4[i];
        a.x = a.x * rs * ww.x;
        a.y = a.y * rs * ww.y;
        a.z = a.z * rs * ww.z;
        a.w = a.w * rs * ww.w;
        o4[i] = a;
    }
}

// ================= bf16 split mma GEMM (NT=3 or 4 terms) ===================
__device__ __forceinline__ uint32_t packbf(__nv_bfloat16 a, __nv_bfloat16 b) {
    __nv_bfloat162 t;
    t.x = a; t.y = b;
    return *(uint32_t*)&t;
}

__device__ __forceinline__ void split4(float4 v, uint2& hi, uint2& lo) {
    __nv_bfloat16 hx = __float2bfloat16(v.x);
    __nv_bfloat16 hy = __float2bfloat16(v.y);
    __nv_bfloat16 hz = __float2bfloat16(v.z);
    __nv_bfloat16 hw = __float2bfloat16(v.w);
    __nv_bfloat16 lx = __float2bfloat16(v.x - __bfloat162float(hx));
    __nv_bfloat16 ly = __float2bfloat16(v.y - __bfloat162float(hy));
    __nv_bfloat16 lz = __float2bfloat16(v.z - __bfloat162float(hz));
    __nv_bfloat16 lw = __float2bfloat16(v.w - __bfloat162float(hw));
    hi.x = packbf(hx, hy); hi.y = packbf(hz, hw);
    lo.x = packbf(lx, ly); lo.y = packbf(lz, lw);
}

__device__ __forceinline__ void mma16(float* c, uint32_t a0, uint32_t a1,
                                      uint32_t a2, uint32_t a3,
                                      uint32_t b0, uint32_t b1) {
    asm volatile(
        "mma.sync.aligned.m16n8k16.row.col.f32.bf16.bf16.f32 "
        "{%0,%1,%2,%3}, {%4,%5,%6,%7}, {%8,%9}, {%0,%1,%2,%3};"
        : "+f"(c[0]), "+f"(c[1]), "+f"(c[2]), "+f"(c[3])
        : "r"(a0), "r"(a1), "r"(a2), "r"(a3), "r"(b0), "r"(b1));
}

#define STRH 40
#define HBUF (128 * STRH)

template <int NT>
__global__ void __launch_bounds__(256) bf16gemm_nt(
    const float* __restrict__ A, const float* __restrict__ B,
    const float* __restrict__ bias, const float* __restrict__ addsrc,
    float* __restrict__ C, int M, int N, int K) {
    extern __shared__ __nv_bfloat16 sh[];
    __nv_bfloat16* Ah = sh;
    __nv_bfloat16* Al = sh + 2 * HBUF;
    __nv_bfloat16* Bh = sh + 4 * HBUF;
    __nv_bfloat16* Bl = sh + 6 * HBUF;

    const int tid = threadIdx.x;
    const int lane = tid & 31;
    const int warp = tid >> 5;
    const int wm = warp & 1;
    const int wn = warp >> 1;
    const int g = lane >> 2;
    const int tg = lane & 3;
    const int bm = blockIdx.y * 128;
    const int bn = blockIdx.x * 128;

    float acc[4][4][4];
#pragma unroll
    for (int i = 0; i < 4; i++)
#pragma unroll
        for (int j = 0; j < 4; j++)
#pragma unroll
            for (int l = 0; l < 4; l++) acc[i][j][l] = 0.f;

    const int lrow = tid >> 3;
    const int lc4 = (tid & 7) * 4;
    const float* Ag = A + (size_t)(bm + lrow) * K + lc4;
    const float* Bg = B + (size_t)(bn + lrow) * K + lc4;

    float4 pa[4], pb[4];
#pragma unroll
    for (int p = 0; p < 4; p++) {
        pa[p] = *(const float4*)(Ag + (size_t)(p * 32) * K);
        pb[p] = *(const float4*)(Bg + (size_t)(p * 32) * K);
    }

    const int NKT = K / 32;

#pragma unroll
    for (int p = 0; p < 4; p++) {
        int row = lrow + p * 32;
        uint2 hi, lo;
        split4(pa[p], hi, lo);
        *(uint2*)(Ah + row * STRH + lc4) = hi;
        *(uint2*)(Al + row * STRH + lc4) = lo;
        split4(pb[p], hi, lo);
        *(uint2*)(Bh + row * STRH + lc4) = hi;
        *(uint2*)(Bl + row * STRH + lc4) = lo;
    }
    __syncthreads();

    for (int kt = 0; kt < NKT; kt++) {
        const int cur = kt & 1;
        const bool more = (kt + 1 < NKT);
        if (more) {
            size_t off = (size_t)(kt + 1) * 32;
#pragma unroll
            for (int p = 0; p < 4; p++) {
                pa[p] = *(const float4*)(Ag + (size_t)(p * 32) * K + off);
                pb[p] = *(const float4*)(Bg + (size_t)(p * 32) * K + off);
            }
        }
        const __nv_bfloat16* Ach = Ah + cur * HBUF;
        const __nv_bfloat16* Acl = Al + cur * HBUF;
        const __nv_bfloat16* Bch = Bh + cur * HBUF;
        const __nv_bfloat16* Bcl = Bl + cur * HBUF;

#pragma unroll
        for (int ks = 0; ks < 2; ks++) {
            const int k = ks * 16;
            uint32_t afh[4][4], afl[4][4], bfh[4][2], bfl[4][2];
#pragma unroll
            for (int mi = 0; mi < 4; mi++) {
                int rb = wm * 64 + mi * 16;
                int i00 = (rb + g) * STRH + k + 2 * tg;
                int i01 = (rb + 8 + g) * STRH + k + 2 * tg;
                afh[mi][0] = *(const uint32_t*)(Ach + i00);
                afh[mi][1] = *(const uint32_t*)(Ach + i01);
                afh[mi][2] = *(const uint32_t*)(Ach + i00 + 8);
                afh[mi][3] = *(const uint32_t*)(Ach + i01 + 8);
                afl[mi][0] = *(const uint32_t*)(Acl + i00);
                afl[mi][1] = *(const uint32_t*)(Acl + i01);
                afl[mi][2] = *(const uint32_t*)(Acl + i00 + 8);
                afl[mi][3] = *(const uint32_t*)(Acl + i01 + 8);
            }
#pragma unroll
            for (int ni = 0; ni < 4; ni++) {
                int nb = wn * 32 + ni * 8;
                int j0 = (nb + g) * STRH + k + 2 * tg;
                bfh[ni][0] = *(const uint32_t*)(Bch + j0);
                bfh[ni][1] = *(const uint32_t*)(Bch + j0 + 8);
                bfl[ni][0] = *(const uint32_t*)(Bcl + j0);
                bfl[ni][1] = *(const uint32_t*)(Bcl + j0 + 8);
            }
#pragma unroll
            for (int mi = 0; mi < 4; mi++)
#pragma unroll
                for (int ni = 0; ni < 4; ni++) {
                    mma16(acc[mi][ni], afh[mi][0], afh[mi][1], afh[mi][2],
                          afh[mi][3], bfh[ni][0], bfh[ni][1]);
                    mma16(acc[mi][ni], afh[mi][0], afh[mi][1], afh[mi][2],
                          afh[mi][3], bfl[ni][0], bfl[ni][1]);
                    mma16(acc[mi][ni], afl[mi][0], afl[mi][1], afl[mi][2],
                          afl[mi][3], bfh[ni][0], bfh[ni][1]);
                    if (NT == 4)
                        mma16(acc[mi][ni], afl[mi][0], afl[mi][1], afl[mi][2],
                              afl[mi][3], bfl[ni][0], bfl[ni][1]);
                }
        }

        if (more) {
            const int nxt = (kt + 1) & 1;
            __nv_bfloat16* Adh = Ah + nxt * HBUF;
            __nv_bfloat16* Adl = Al + nxt * HBUF;
            __nv_bfloat16* Bdh = Bh + nxt * HBUF;
            __nv_bfloat16* Bdl = Bl + nxt * HBUF;
#pragma unroll
            for (int p = 0; p < 4; p++) {
                int row = lrow + p * 32;
                uint2 hi, lo;
                split4(pa[p], hi, lo);
                *(uint2*)(Adh + row * STRH + lc4) = hi;
                *(uint2*)(Adl + row * STRH + lc4) = lo;
                split4(pb[p], hi, lo);
                *(uint2*)(Bdh + row * STRH + lc4) = hi;
                *(uint2*)(Bdl + row * STRH + lc4) = lo;
            }
        }
        __syncthreads();
    }

#pragma unroll
    for (int mi = 0; mi < 4; mi++) {
        int r0 = bm + wm * 64 + mi * 16 + g;
#pragma unroll
        for (int ni = 0; ni < 4; ni++) {
            int col = bn + wn * 32 + ni * 8 + tg * 2;
            float2 v0, v1;
            v0.x = acc[mi][ni][0]; v0.y = acc[mi][ni][1];
            v1.x = acc[mi][ni][2]; v1.y = acc[mi][ni][3];
            if (bias) {
                float2 bb = *(const float2*)(bias + col);
                v0.x += bb.x; v0.y += bb.y;
                v1.x += bb.x; v1.y += bb.y;
            }
            size_t i0 = (size_t)r0 * N + col;
            size_t i1 = (size_t)(r0 + 8) * N + col;
            if (addsrc) {
                float2 s0 = *(const float2*)(addsrc + i0);
                float2 s1 = *(const float2*)(addsrc + i1);
                v0.x += s0.x; v0.y += s0.y;
                v1.x += s1.x; v1.y += s1.y;
            }
            *(float2*)(C + i0) = v0;
            *(float2*)(C + i1) = v1;
        }
    }
}

// ---------------- RoPE (position_ids int32) ----------------
__global__ void rope_kernel(float* __restrict__ q, float* __restrict__ k,
                            const int* __restrict__ pos) {
    int idx = blockIdx.x * 256 + threadIdx.x;
    if (idx >= TT * NH * 64) return;
    int j = idx & 63;
    int th = idx >> 6;
    int t = th >> 5;
    float p = (float)pos[t];
    float ang = p * exp2f(-(float)j * (13.287712379549449f / 64.f));
    float s, c;
    sincosf(ang, &s, &c);
    size_t base = (size_t)th * HD + j;
    float q0 = q[base], q1 = q[base + 64];
    q[base] = q0 * c - q1 * s;
    q[base + 64] = q1 * c + q0 * s;
    float k0 = k[base], k1 = k[base + 64];
    k[base] = k0 * c - k1 * s;
    k[base + 64] = k1 * c + k0 * s;
}

// ---------------- attn predictor logits (exact; reads exact ln1-hs) --------
__global__ void attn_pred_kernel(const float* __restrict__ hs,
                                 const float* __restrict__ w,
                                 const float* __restrict__ b,
                                 float* __restrict__ out) {
    int t = blockIdx.x;
    int warp = threadIdx.x >> 5, lane = threadIdx.x & 31;
    const float* hsrow = hs + (size_t)t * HH;
    for (int hh = 0; hh < 4; hh++) {
        int h = warp * 4 + hh;
        const float* wr = w + (size_t)h * HH;
        float s = 0.f;
        for (int kk = lane; kk < HH; kk += 32) s += hsrow[kk] * wr[kk];
        for (int o = 16; o > 0; o >>= 1) s += __shfl_xor_sync(0xffffffffu, s, o);
        if (lane == 0) out[t * NH + h] = s + b[h];
    }
}

// ---------------- head top-16 mask ----------------
__global__ void head_mask_kernel(const float* __restrict__ logit,
                                 float* __restrict__ mask) {
    int t = blockIdx.x;
    int h = threadIdx.x;
    float v = logit[t * NH + h];
    int rank = 0;
    for (int j = 0; j < NH; j++) {
        float vj = logit[t * NH + j];
        rank += (vj > v) || (vj == v && j < h);
    }
    mask[t * NH + h] = (rank < ATTN_TOPK) ? 1.f : 0.f;
}

// ---------------- attention: 8 q-rows per block, two-pass softmax ----------
__global__ void __launch_bounds__(128)
attention8_kernel(const float* __restrict__ q, const float* __restrict__ k,
                  const float* __restrict__ v, const float* __restrict__ hmask,
                  const int* __restrict__ amask, float* __restrict__ out) {
    extern __shared__ float asm_[];
    float* qs = asm_;                 // QB*HD
    float* P = asm_ + QB * HD;        // TT*QB
    __shared__ float red[128];
    const int t0 = blockIdx.x * QB;
    const int h = blockIdx.y;
    const int tid = threadIdx.x;
    const float NEGF = -3.4e38f;

    float act[QB];
    bool anyact = false;
#pragma unroll
    for (int r = 0; r < QB; r++) {
        act[r] = hmask[(t0 + r) * NH + h];
        anyact |= (act[r] != 0.f);
    }
    if (!anyact) {
#pragma unroll
        for (int r = 0; r < QB; r++)
            out[(size_t)(t0 + r) * HH + h * HD + tid] = 0.f;
        return;
    }
#pragma unroll
    for (int r = 0; r < QB; r++)
        qs[r * HD + tid] = q[(size_t)(t0 + r) * HH + h * HD + tid] *
                           0.08838834764831845f;
    __syncthreads();

    const int nk = t0 + QB;
    float lm[QB];
#pragma unroll
    for (int r = 0; r < QB; r++) lm[r] = NEGF;

    for (int j = tid; j < nk; j += 128) {
        float s[QB];
#pragma unroll
        for (int r = 0; r < QB; r++) s[r] = 0.f;
        bool am = (amask[j] != 0);
        if (am) {
            const float4* kr = (const float4*)(k + (size_t)j * HH + h * HD);
#pragma unroll
            for (int d4 = 0; d4 < 32; d4++) {
                float4 kv = kr[d4];
#pragma unroll
                for (int r = 0; r < QB; r++) {
                    float4 qv = *(const float4*)(qs + r * HD + d4 * 4);
                    s[r] += qv.x * kv.x + qv.y * kv.y + qv.z * kv.z +
                            qv.w * kv.w;
                }
            }
        }
        float val[QB];
#pragma unroll
        for (int r = 0; r < QB; r++) {
            val[r] = (am && j <= t0 + r) ? s[r] : NEGF;
            lm[r] = fmaxf(lm[r], val[r]);
        }
        float4 o0, o1;
        o0.x = val[0]; o0.y = val[1]; o0.z = val[2]; o0.w = val[3];
        o1.x = val[4]; o1.y = val[5]; o1.z = val[6]; o1.w = val[7];
        ((float4*)(P + j * QB))[0] = o0;
        ((float4*)(P + j * QB))[1] = o1;
    }
    float M[QB];
#pragma unroll
    for (int r = 0; r < QB; r++) {
        red[tid] = lm[r];
        __syncthreads();
        for (int o = 64; o > 0; o >>= 1) {
            if (tid < o) red[tid] = fmaxf(red[tid], red[tid + o]);
            __syncthreads();
        }
        M[r] = red[0];
        __syncthreads();
    }
    float ls[QB];
#pragma unroll
    for (int r = 0; r < QB; r++) ls[r] = 0.f;
    for (int j = tid; j < nk; j += 128) {
        float4 a = ((float4*)(P + j * QB))[0];
        float4 b = ((float4*)(P + j * QB))[1];
        a.x = __expf(a.x - M[0]); a.y = __expf(a.y - M[1]);
        a.z = __expf(a.z - M[2]); a.w = __expf(a.w - M[3]);
        b.x = __expf(b.x - M[4]); b.y = __expf(b.y - M[5]);
        b.z = __expf(b.z - M[6]); b.w = __expf(b.w - M[7]);
        ls[0] += a.x; ls[1] += a.y; ls[2] += a.z; ls[3] += a.w;
        ls[4] += b.x; ls[5] += b.y; ls[6] += b.z; ls[7] += b.w;
        ((float4*)(P + j * QB))[0] = a;
        ((float4*)(P + j * QB))[1] = b;
    }
    float inv[QB];
#pragma unroll
    for (int r = 0; r < QB; r++) {
        red[tid] = ls[r];
        __syncthreads();
        for (int o = 64; o > 0; o >>= 1) {
            if (tid < o) red[tid] += red[tid + o];
            __syncthreads();
        }
        inv[r] = 1.f / red[0];
        __syncthreads();
    }
    float acc[QB];
#pragma unroll
    for (int r = 0; r < QB; r++) acc[r] = 0.f;
#pragma unroll 4
    for (int j = 0; j < nk; j++) {
        float vv = v[(size_t)j * HH + h * HD + tid];
        float4 a = ((float4*)(P + j * QB))[0];
        float4 b = ((float4*)(P + j * QB))[1];
        acc[0] = fmaf(a.x, vv, acc[0]); acc[1] = fmaf(a.y, vv, acc[1]);
        acc[2] = fmaf(a.z, vv, acc[2]); acc[3] = fmaf(a.w, vv, acc[3]);
        acc[4] = fmaf(b.x, vv, acc[4]); acc[5] = fmaf(b.y, vv, acc[5]);
        acc[6] = fmaf(b.z, vv, acc[6]); acc[7] = fmaf(b.w, vv, acc[7]);
    }
#pragma unroll
    for (int r = 0; r < QB; r++)
        out[(size_t)(t0 + r) * HH + h * HD + tid] =
            (act[r] != 0.f) ? acc[r] * inv[r] : 0.f;
}

// ---------------- top-k radix select machinery ----------------
__device__ __forceinline__ unsigned fkey(float x) {
    unsigned b = __float_as_uint(x);
    return (b & 0x80000000u) ? ~b : (b | 0x80000000u);
}
__device__ __forceinline__ float unfkey(unsigned k) {
    unsigned b = (k & 0x80000000u) ? (k & 0x7fffffffu) : ~k;
    return __uint_as_float(b);
}

__global__ void mlp_thresh_kernel(const float* __restrict__ logits,
                                  float* __restrict__ thr) {
    int row = blockIdx.x;
    const float* lr = logits + (size_t)row * II;
    __shared__ unsigned hist[256];
    __shared__ unsigned sh_sel, sh_kk;
    int tid = threadIdx.x;
    unsigned prefix = 0;
    unsigned kk = MLP_TOPK;
    for (int shift = 24; shift >= 0; shift -= 8) {
        hist[tid] = 0;
        __syncthreads();
        for (int i = tid; i < II; i += 256) {
            unsigned u = fkey(lr[i]);
            bool ok = (shift == 24) || ((u >> (shift + 8)) == prefix);
            if (ok) atomicAdd(&hist[(u >> shift) & 255u], 1u);
        }
        __syncthreads();
        if (tid == 0) {
            unsigned c = 0;
            int sel = 0;
            for (int b = 255; b >= 0; b--) {
                c += hist[b];
                if (c >= kk) { sel = b; break; }
            }
            sh_sel = (unsigned)sel;
            sh_kk = kk - (c - hist[sel]);
        }
        __syncthreads();
        prefix = (prefix << 8) | sh_sel;
        kk = sh_kk;
        __syncthreads();
    }
    if (tid == 0) thr[row] = unfkey(prefix);
}

#define BAND 4e-3f
__global__ void mlp_correct_kernel(float* __restrict__ mlog,
                                   const float* __restrict__ hs,
                                   const float* __restrict__ w,
                                   const float* __restrict__ b,
                                   const float* __restrict__ thr) {
    int row = blockIdx.x;
    int tid = threadIdx.x;
    __shared__ int cnt;
    __shared__ int idxs[1024];
    if (tid == 0) cnt = 0;
    __syncthreads();
    float th = thr[row];
    float* lr = mlog + (size_t)row * II;
    for (int i = tid; i < II; i += 256) {
        if (fabsf(lr[i] - th) <= BAND) {
            int p = atomicAdd(&cnt, 1);
            if (p < 1024) idxs[p] = i;
        }
    }
    __syncthreads();
    int n = cnt < 1024 ? cnt : 1024;
    int warp = tid >> 5, lane = tid & 31;
    const float* hsr = hs + (size_t)row * HH;
    for (int c = warp; c < n; c += 8) {
        int i = idxs[c];
        const float* wr = w + (size_t)i * HH;
        float s = 0.f;
        for (int kk = lane; kk < HH; kk += 32) s += hsr[kk] * wr[kk];
        for (int o = 16; o > 0; o >>= 1) s += __shfl_xor_sync(0xffffffffu, s, o);
        if (lane == 0) lr[i] = s + b[i];
    }
}

__global__ void mlp_topk_kernel(const float* __restrict__ logits,
                                float* __restrict__ mask) {
    int row = blockIdx.x;
    const float* lr = logits + (size_t)row * II;
    __shared__ unsigned hist[256];
    __shared__ unsigned sh_sel, sh_kk;
    __shared__ unsigned sh_cnt[2];
    int tid = threadIdx.x;
    unsigned prefix = 0;
    unsigned kk = MLP_TOPK;
    for (int shift = 24; shift >= 0; shift -= 8) {
        hist[tid] = 0;
        __syncthreads();
        for (int i = tid; i < II; i += 256) {
            unsigned u = fkey(lr[i]);
            bool ok = (shift == 24) || ((u >> (shift + 8)) == prefix);
            if (ok) atomicAdd(&hist[(u >> shift) & 255u], 1u);
        }
        __syncthreads();
        if (tid == 0) {
            unsigned c = 0;
            int sel = 0;
            for (int b = 255; b >= 0; b--) {
                c += hist[b];
                if (c >= kk) { sel = b; break; }
            }
            sh_sel = (unsigned)sel;
            sh_kk = kk - (c - hist[sel]);
        }
        __syncthreads();
        prefix = (prefix << 8) | sh_sel;
        kk = sh_kk;
        __syncthreads();
    }
    unsigned thresh = prefix;
    if (tid < 2) sh_cnt[tid] = 0;
    __syncthreads();
    unsigned lg = 0, le = 0;
    for (int i = tid; i < II; i += 256) {
        unsigned u = fkey(lr[i]);
        if (u > thresh) lg++;
        else if (u == thresh) le++;
    }
    atomicAdd(&sh_cnt[0], lg);
    atomicAdd(&sh_cnt[1], le);
    __syncthreads();
    unsigned g = sh_cnt[0], e = sh_cnt[1];
    float* mr = mask + (size_t)row * II;
    if (g + e == MLP_TOPK) {
        for (int i = tid; i < II; i += 256)
            mr[i] = (fkey(lr[i]) >= thresh) ? 1.f : 0.f;
    } else {
        for (int i = tid; i < II; i += 256)
            mr[i] = (fkey(lr[i]) > thresh) ? 1.f : 0.f;
        __syncthreads();
        if (tid == 0) {
            unsigned quota = MLP_TOPK - g;
            for (int i = 0; i < II && quota > 0; i++) {
                if (fkey(lr[i]) == thresh) { mr[i] = 1.f; quota--; }
            }
        }
    }
}

// ---------------- silu * up * mask ----------------
__global__ void silu_mul_mask_kernel(float* __restrict__ gate,
                                     const float* __restrict__ up,
                                     const float* __restrict__ mask, int n) {
    int i = blockIdx.x * 256 + threadIdx.x;
    if (i < n) {
        float x = gate[i];
        float si = x / (1.f + __expf(-x));
        gate[i] = si * up[i] * mask[i];
    }
}

// ---------------- launch ----------------
extern "C" void kernel_launch(void* const* d_in, const int* in_sizes, int n_in,
                              void* d_out, int out_size) {
    const float* hidden = (const float*)d_in[0];
    const int* amask = (const int*)d_in[1];
    const int* pos = (const int*)d_in[2];
    const float* wq = (const float*)d_in[3];
    const float* wk = (const float*)d_in[4];
    const float* wv = (const float*)d_in[5];
    const float* wo = (const float*)d_in[6];
    const float* w_gate = (const float*)d_in[7];
    const float* w_up = (const float*)d_in[8];
    const float* w_down = (const float*)d_in[9];
    const float* ln1 = (const float*)d_in[10];
    const float* ln2 = (const float*)d_in[11];
    const float* apw = (const float*)d_in[12];
    const float* apb = (const float*)d_in[13];
    const float* mpw = (const float*)d_in[14];
    const float* mpb = (const float*)d_in[15];
    float* out = (float*)d_out;

    float *hs, *q, *k, *v, *attn, *res2, *hlog, *hmask, *mlog, *fcm, *gate, *up,
        *thr;
    cudaGetSymbolAddress((void**)&hs, g_hs);
    cudaGetSymbolAddress((void**)&q, g_q);
    cudaGetSymbolAddress((void**)&k, g_k);
    cudaGetSymbolAddress((void**)&v, g_v);
    cudaGetSymbolAddress((void**)&attn, g_attn);
    cudaGetSymbolAddress((void**)&res2, g_res2);
    cudaGetSymbolAddress((void**)&hlog, g_hlogit);
    cudaGetSymbolAddress((void**)&hmask, g_headmask);
    cudaGetSymbolAddress((void**)&mlog, g_mlogit);
    cudaGetSymbolAddress((void**)&fcm, g_fcmask);
    cudaGetSymbolAddress((void**)&gate, g_gate);
    cudaGetSymbolAddress((void**)&up, g_up);
    cudaGetSymbolAddress((void**)&thr, g_thr);

    const int SMEM_B = 8 * HBUF * (int)sizeof(__nv_bfloat16);   // 81920 B
    cudaFuncSetAttribute(bf16gemm_nt<3>,
                         cudaFuncAttributeMaxDynamicSharedMemorySize, SMEM_B);
    cudaFuncSetAttribute(bf16gemm_nt<4>,
                         cudaFuncAttributeMaxDynamicSharedMemorySize, SMEM_B);
    const int SMEM_A = (QB * HD + TT * QB) * (int)sizeof(float);  // 69632 B
    cudaFuncSetAttribute(attention8_kernel,
                         cudaFuncAttributeMaxDynamicSharedMemorySize, SMEM_A);

    dim3 gHH(HH / 128, TT / 128);
    dim3 gII(II / 128, TT / 128);

    rmsnorm_kernel<<<TT, 256>>>(hidden, ln1, hs);
    // q/k/v/wo: bf16x4 (sigma ~4e-6, attenuated through attention chain)
    bf16gemm_nt<4><<<gHH, 256, SMEM_B>>>(hs, wq, nullptr, nullptr, q, TT, HH, HH);
    bf16gemm_nt<4><<<gHH, 256, SMEM_B>>>(hs, wk, nullptr, nullptr, k, TT, HH, HH);
    bf16gemm_nt<4><<<gHH, 256, SMEM_B>>>(hs, wv, nullptr, nullptr, v, TT, HH, HH);
    rope_kernel<<<(TT * NH * 64 + 255) / 256, 256>>>(q, k, pos);
    attn_pred_kernel<<<TT, 256>>>(hs, apw, apb, hlog);
    head_mask_kernel<<<TT, 32>>>(hlog, hmask);
    attention8_kernel<<<dim3(TT / QB, NH), 128, SMEM_A>>>(q, k, v, hmask, amask,
                                                          attn);
    bf16gemm_nt<4><<<gHH, 256, SMEM_B>>>(attn, wo, nullptr, hidden, res2, TT, HH, HH);
    rmsnorm_kernel<<<TT, 256>>>(res2, ln2, hs);
    // mlogit: bf16x3 + exact band repair -> selection fp32-exact
    bf16gemm_nt<3><<<gII, 256, SMEM_B>>>(hs, mpw, mpb, nullptr, mlog, TT, II, HH);
    mlp_thresh_kernel<<<TT, 256>>>(mlog, thr);
    mlp_correct_kernel<<<TT, 256>>>(mlog, hs, mpw, mpb, thr);
    mlp_topk_kernel<<<TT, 256>>>(mlog, fcm);
    // direct-output GEMMs: bf16x3
    bf16gemm_nt<3><<<gII, 256, SMEM_B>>>(hs, w_gate, nullptr, nullptr, gate, TT, II, HH);
    bf16gemm_nt<3><<<gII, 256, SMEM_B>>>(hs, w_up, nullptr, nullptr, up, TT, II, HH);
    silu_mul_mask_kernel<<<(TT * II + 255) / 256, 256>>>(gate, up, fcm, TT * II);
    bf16gemm_nt<3><<<gHH, 256, SMEM_B>>>(gate, w_down, nullptr, res2, out, TT, HH, II);
}

// round 12
// speedup vs baseline: 2.8655x; 1.0295x over previous
#include <cuda_runtime.h>
#include <cuda_bf16.h>
#include <math.h>
#include <stdint.h>

#define TT 2048
#define HH 4096
#define NH 32
#define HD 128
#define II 11008
#define ATTN_TOPK 16
#define MLP_TOPK 2048
#define QB 8

// ---------------- scratch ----------------
__device__ float g_hs[TT * HH];
__device__ float g_q[TT * HH];
__device__ float g_k[TT * HH];
__device__ float g_v[TT * HH];
__device__ float g_attn[TT * HH];
__device__ float g_res2[TT * HH];
__device__ float g_hlogit[TT * NH];
__device__ float g_headmask[TT * NH];
__device__ float g_mlogit[TT * II];
__device__ float g_fcmask[TT * II];
__device__ float g_gate[TT * II];
__device__ float g_up[TT * II];
__device__ float g_thr[TT];

// ---------------- RMSNorm ----------------
__global__ void rmsnorm_kernel(const float* __restrict__ x,
                               const float* __restrict__ w,
                               float* __restrict__ out) {
    int row = blockIdx.x;
    const float4* x4 = (const float4*)(x + (size_t)row * HH);
    const float4* w4 = (const float4*)w;
    float s = 0.f;
    for (int i = threadIdx.x; i < HH / 4; i += 256) {
        float4 v = x4[i];
        s += v.x * v.x + v.y * v.y + v.z * v.z + v.w * v.w;
    }
    __shared__ float red[256];
    red[threadIdx.x] = s;
    __syncthreads();
    for (int o = 128; o > 0; o >>= 1) {
        if (threadIdx.x < o) red[threadIdx.x] += red[threadIdx.x + o];
        __syncthreads();
    }
    float rs = rsqrtf(red[0] / (float)HH + 1e-6f);
    float4* o4 = (float4*)(out + (size_t)row * HH);
    for (int i = threadIdx.x; i < HH / 4; i += 256) {
        float4 a = x4[i];
        float4 ww = w4[i];
        a.x = a.x * rs * ww.x;
        a.y = a.y * rs * ww.y;
        a.z = a.z * rs * ww.z;
        a.w = a.w * rs * ww.w;
        o4[i] = a;
    }
}

// ================= bf16 split mma GEMM (NT=3 or 4), ldmatrix frags =========
__device__ __forceinline__ uint32_t packbf(__nv_bfloat16 a, __nv_bfloat16 b) {
    __nv_bfloat162 t;
    t.x = a; t.y = b;
    return *(uint32_t*)&t;
}

__device__ __forceinline__ void split4(float4 v, uint2& hi, uint2& lo) {
    __nv_bfloat16 hx = __float2bfloat16(v.x);
    __nv_bfloat16 hy = __float2bfloat16(v.y);
    __nv_bfloat16 hz = __float2bfloat16(v.z);
    __nv_bfloat16 hw = __float2bfloat16(v.w);
    __nv_bfloat16 lx = __float2bfloat16(v.x - __bfloat162float(hx));
    __nv_bfloat16 ly = __float2bfloat16(v.y - __bfloat162float(hy));
    __nv_bfloat16 lz = __float2bfloat16(v.z - __bfloat162float(hz));
    __nv_bfloat16 lw = __float2bfloat16(v.w - __bfloat162float(hw));
    hi.x = packbf(hx, hy); hi.y = packbf(hz, hw);
    lo.x = packbf(lx, ly); lo.y = packbf(lz, lw);
}

__device__ __forceinline__ void mma16(float* c, uint32_t a0, uint32_t a1,
                                      uint32_t a2, uint32_t a3,
                                      uint32_t b0, uint32_t b1) {
    asm volatile(
        "mma.sync.aligned.m16n8k16.row.col.f32.bf16.bf16.f32 "
        "{%0,%1,%2,%3}, {%4,%5,%6,%7}, {%8,%9}, {%0,%1,%2,%3};"
        : "+f"(c[0]), "+f"(c[1]), "+f"(c[2]), "+f"(c[3])
        : "r"(a0), "r"(a1), "r"(a2), "r"(a3), "r"(b0), "r"(b1));
}

__device__ __forceinline__ void ldsm4(uint32_t addr, uint32_t& r0, uint32_t& r1,
                                      uint32_t& r2, uint32_t& r3) {
    asm volatile(
        "ldmatrix.sync.aligned.m8n8.x4.shared.b16 {%0,%1,%2,%3}, [%4];"
        : "=r"(r0), "=r"(r1), "=r"(r2), "=r"(r3) : "r"(addr));
}

__device__ __forceinline__ uint32_t smem_u32(const void* p) {
    uint32_t a;
    asm("{ .reg .u64 t; cvta.to.shared.u64 t, %1; cvt.u32.u64 %0, t; }"
        : "=r"(a) : "l"(p));
    return a;
}

#define STRH 40
#define HBUF (128 * STRH)

template <int NT>
__global__ void __launch_bounds__(256) bf16gemm_nt(
    const float* __restrict__ A, const float* __restrict__ B,
    const float* __restrict__ bias, const float* __restrict__ addsrc,
    float* __restrict__ C, int M, int N, int K) {
    extern __shared__ __nv_bfloat16 sh[];
    __nv_bfloat16* Ah = sh;
    __nv_bfloat16* Al = sh + 2 * HBUF;
    __nv_bfloat16* Bh = sh + 4 * HBUF;
    __nv_bfloat16* Bl = sh + 6 * HBUF;
    const uint32_t shU = smem_u32(sh);

    const int tid = threadIdx.x;
    const int lane = tid & 31;
    const int warp = tid >> 5;
    const int wm = warp & 1;
    const int wn = warp >> 1;
    const int bm = blockIdx.y * 128;
    const int bn = blockIdx.x * 128;

    // ldmatrix per-lane offsets (in halves)
    // A x4: m0=rows rb..+7 @k, m1=rows rb+8..15 @k, m2=rb..+7 @k+8, m3=rb+8..15 @k+8
    const uint32_t arow = (uint32_t)(lane & 15) * STRH + (uint32_t)(lane >> 4) * 8;
    // B x4 (covers ni-pair): m0=nb..+7@k, m1=nb..+7@k+8, m2=nb+8..15@k, m3=nb+8..15@k+8
    const uint32_t brow = (uint32_t)(8 * (lane >> 4) + (lane & 7)) * STRH +
                          (uint32_t)((lane >> 3) & 1) * 8;

    float acc[4][4][4];
#pragma unroll
    for (int i = 0; i < 4; i++)
#pragma unroll
        for (int j = 0; j < 4; j++)
#pragma unroll
            for (int l = 0; l < 4; l++) acc[i][j][l] = 0.f;

    const int lrow = tid >> 3;
    const int lc4 = (tid & 7) * 4;
    const float* Ag = A + (size_t)(bm + lrow) * K + lc4;
    const float* Bg = B + (size_t)(bn + lrow) * K + lc4;

    float4 pa[4], pb[4];
#pragma unroll
    for (int p = 0; p < 4; p++) {
        pa[p] = *(const float4*)(Ag + (size_t)(p * 32) * K);
        pb[p] = *(const float4*)(Bg + (size_t)(p * 32) * K);
    }

    const int NKT = K / 32;

#pragma unroll
    for (int p = 0; p < 4; p++) {
        int row = lrow + p * 32;
        uint2 hi, lo;
        split4(pa[p], hi, lo);
        *(uint2*)(Ah + row * STRH + lc4) = hi;
        *(uint2*)(Al + row * STRH + lc4) = lo;
        split4(pb[p], hi, lo);
        *(uint2*)(Bh + row * STRH + lc4) = hi;
        *(uint2*)(Bl + row * STRH + lc4) = lo;
    }
    __syncthreads();

    for (int kt = 0; kt < NKT; kt++) {
        const int cur = kt & 1;
        const bool more = (kt + 1 < NKT);
        if (more) {
            size_t off = (size_t)(kt + 1) * 32;
#pragma unroll
            for (int p = 0; p < 4; p++) {
                pa[p] = *(const float4*)(Ag + (size_t)(p * 32) * K + off);
                pb[p] = *(const float4*)(Bg + (size_t)(p * 32) * K + off);
            }
        }
        const uint32_t AhU = shU + 2u * (cur * HBUF);
        const uint32_t AlU = shU + 2u * (2 * HBUF + cur * HBUF);
        const uint32_t BhU = shU + 2u * (4 * HBUF + cur * HBUF);
        const uint32_t BlU = shU + 2u * (6 * HBUF + cur * HBUF);

#pragma unroll
        for (int ks = 0; ks < 2; ks++) {
            const uint32_t k = ks * 16;
            uint32_t afh[4][4], afl[4][4], bfh[4][2], bfl[4][2];
#pragma unroll
            for (int mi = 0; mi < 4; mi++) {
                uint32_t ro = (uint32_t)(wm * 64 + mi * 16) * STRH + arow + k;
                ldsm4(AhU + 2u * ro, afh[mi][0], afh[mi][1], afh[mi][2],
                      afh[mi][3]);
                ldsm4(AlU + 2u * ro, afl[mi][0], afl[mi][1], afl[mi][2],
                      afl[mi][3]);
            }
#pragma unroll
            for (int p = 0; p < 2; p++) {
                uint32_t ro = (uint32_t)(wn * 32 + p * 16) * STRH + brow + k;
                ldsm4(BhU + 2u * ro, bfh[2 * p][0], bfh[2 * p][1],
                      bfh[2 * p + 1][0], bfh[2 * p + 1][1]);
                ldsm4(BlU + 2u * ro, bfl[2 * p][0], bfl[2 * p][1],
                      bfl[2 * p + 1][0], bfl[2 * p + 1][1]);
            }
#pragma unroll
            for (int mi = 0; mi < 4; mi++)
#pragma unroll
                for (int ni = 0; ni < 4; ni++) {
                    mma16(acc[mi][ni], afh[mi][0], afh[mi][1], afh[mi][2],
                          afh[mi][3], bfh[ni][0], bfh[ni][1]);
                    mma16(acc[mi][ni], afh[mi][0], afh[mi][1], afh[mi][2],
                          afh[mi][3], bfl[ni][0], bfl[ni][1]);
                    mma16(acc[mi][ni], afl[mi][0], afl[mi][1], afl[mi][2],
                          afl[mi][3], bfh[ni][0], bfh[ni][1]);
                    if (NT == 4)
                        mma16(acc[mi][ni], afl[mi][0], afl[mi][1], afl[mi][2],
                              afl[mi][3], bfl[ni][0], bfl[ni][1]);
                }
        }

        if (more) {
            const int nxt = (kt + 1) & 1;
            __nv_bfloat16* Adh = Ah + nxt * HBUF;
            __nv_bfloat16* Adl = Al + nxt * HBUF;
            __nv_bfloat16* Bdh = Bh + nxt * HBUF;
            __nv_bfloat16* Bdl = Bl + nxt * HBUF;
#pragma unroll
            for (int p = 0; p < 4; p++) {
                int row = lrow + p * 32;
                uint2 hi, lo;
                split4(pa[p], hi, lo);
                *(uint2*)(Adh + row * STRH + lc4) = hi;
                *(uint2*)(Adl + row * STRH + lc4) = lo;
                split4(pb[p], hi, lo);
                *(uint2*)(Bdh + row * STRH + lc4) = hi;
                *(uint2*)(Bdl + row * STRH + lc4) = lo;
            }
        }
        __syncthreads();
    }

    const int g = lane >> 2;
    const int tg = lane & 3;
#pragma unroll
    for (int mi = 0; mi < 4; mi++) {
        int r0 = bm + wm * 64 + mi * 16 + g;
#pragma unroll
        for (int ni = 0; ni < 4; ni++) {
            int col = bn + wn * 32 + ni * 8 + tg * 2;
            float2 v0, v1;
            v0.x = acc[mi][ni][0]; v0.y = acc[mi][ni][1];
            v1.x = acc[mi][ni][2]; v1.y = acc[mi][ni][3];
            if (bias) {
                float2 bb = *(const float2*)(bias + col);
                v0.x += bb.x; v0.y += bb.y;
                v1.x += bb.x; v1.y += bb.y;
            }
            size_t i0 = (size_t)r0 * N + col;
            size_t i1 = (size_t)(r0 + 8) * N + col;
            if (addsrc) {
                float2 s0 = *(const float2*)(addsrc + i0);
                float2 s1 = *(const float2*)(addsrc + i1);
                v0.x += s0.x; v0.y += s0.y;
                v1.x += s1.x; v1.y += s1.y;
            }
            *(float2*)(C + i0) = v0;
            *(float2*)(C + i1) = v1;
        }
    }
}

// ---------------- RoPE (position_ids int32) ----------------
__global__ void rope_kernel(float* __restrict__ q, float* __restrict__ k,
                            const int* __restrict__ pos) {
    int idx = blockIdx.x * 256 + threadIdx.x;
    if (idx >= TT * NH * 64) return;
    int j = idx & 63;
    int th = idx >> 6;
    int t = th >> 5;
    float p = (float)pos[t];
    float ang = p * exp2f(-(float)j * (13.287712379549449f / 64.f));
    float s, c;
    sincosf(ang, &s, &c);
    size_t base = (size_t)th * HD + j;
    float q0 = q[base], q1 = q[base + 64];
    q[base] = q0 * c - q1 * s;
    q[base + 64] = q1 * c + q0 * s;
    float k0 = k[base], k1 = k[base + 64];
    k[base] = k0 * c - k1 * s;
    k[base + 64] = k1 * c + k0 * s;
}

// ---------------- attn predictor logits (exact; reads exact ln1-hs) --------
__global__ void attn_pred_kernel(const float* __restrict__ hs,
                                 const float* __restrict__ w,
                                 const float* __restrict__ b,
                                 float* __restrict__ out) {
    int t = blockIdx.x;
    int warp = threadIdx.x >> 5, lane = threadIdx.x & 31;
    const float* hsrow = hs + (size_t)t * HH;
    for (int hh = 0; hh < 4; hh++) {
        int h = warp * 4 + hh;
        const float* wr = w + (size_t)h * HH;
        float s = 0.f;
        for (int kk = lane; kk < HH; kk += 32) s += hsrow[kk] * wr[kk];
        for (int o = 16; o > 0; o >>= 1) s += __shfl_xor_sync(0xffffffffu, s, o);
        if (lane == 0) out[t * NH + h] = s + b[h];
    }
}

// ---------------- head top-16 mask ----------------
__global__ void head_mask_kernel(const float* __restrict__ logit,
                                 float* __restrict__ mask) {
    int t = blockIdx.x;
    int h = threadIdx.x;
    float v = logit[t * NH + h];
    int rank = 0;
    for (int j = 0; j < NH; j++) {
        float vj = logit[t * NH + j];
        rank += (vj > v) || (vj == v && j < h);
    }
    mask[t * NH + h] = (rank < ATTN_TOPK) ? 1.f : 0.f;
}

// ---------------- attention: 8 q-rows per block, two-pass softmax ----------
__global__ void __launch_bounds__(128)
attention8_kernel(const float* __restrict__ q, const float* __restrict__ k,
                  const float* __restrict__ v, const float* __restrict__ hmask,
                  const int* __restrict__ amask, float* __restrict__ out) {
    extern __shared__ float asm_[];
    float* qs = asm_;                 // QB*HD
    float* P = asm_ + QB * HD;        // TT*QB
    __shared__ float red[128];
    const int t0 = blockIdx.x * QB;
    const int h = blockIdx.y;
    const int tid = threadIdx.x;
    const float NEGF = -3.4e38f;

    float act[QB];
    bool anyact = false;
#pragma unroll
    for (int r = 0; r < QB; r++) {
        act[r] = hmask[(t0 + r) * NH + h];
        anyact |= (act[r] != 0.f);
    }
    if (!anyact) {
#pragma unroll
        for (int r = 0; r < QB; r++)
            out[(size_t)(t0 + r) * HH + h * HD + tid] = 0.f;
        return;
    }
#pragma unroll
    for (int r = 0; r < QB; r++)
        qs[r * HD + tid] = q[(size_t)(t0 + r) * HH + h * HD + tid] *
                           0.08838834764831845f;
    __syncthreads();

    const int nk = t0 + QB;
    float lm[QB];
#pragma unroll
    for (int r = 0; r < QB; r++) lm[r] = NEGF;

    for (int j = tid; j < nk; j += 128) {
        float s[QB];
#pragma unroll
        for (int r = 0; r < QB; r++) s[r] = 0.f;
        bool am = (amask[j] != 0);
        if (am) {
            const float4* kr = (const float4*)(k + (size_t)j * HH + h * HD);
#pragma unroll
            for (int d4 = 0; d4 < 32; d4++) {
                float4 kv = kr[d4];
#pragma unroll
                for (int r = 0; r < QB; r++) {
                    float4 qv = *(const float4*)(qs + r * HD + d4 * 4);
                    s[r] += qv.x * kv.x + qv.y * kv.y + qv.z * kv.z +
                            qv.w * kv.w;
                }
            }
        }
        float val[QB];
#pragma unroll
        for (int r = 0; r < QB; r++) {
            val[r] = (am && j <= t0 + r) ? s[r] : NEGF;
            lm[r] = fmaxf(lm[r], val[r]);
        }
        float4 o0, o1;
        o0.x = val[0]; o0.y = val[1]; o0.z = val[2]; o0.w = val[3];
        o1.x = val[4]; o1.y = val[5]; o1.z = val[6]; o1.w = val[7];
        ((float4*)(P + j * QB))[0] = o0;
        ((float4*)(P + j * QB))[1] = o1;
    }
    float M[QB];
#pragma unroll
    for (int r = 0; r < QB; r++) {
        red[tid] = lm[r];
        __syncthreads();
        for (int o = 64; o > 0; o >>= 1) {
            if (tid < o) red[tid] = fmaxf(red[tid], red[tid + o]);
            __syncthreads();
        }
        M[r] = red[0];
        __syncthreads();
    }
    float ls[QB];
#pragma unroll
    for (int r = 0; r < QB; r++) ls[r] = 0.f;
    for (int j = tid; j < nk; j += 128) {
        float4 a = ((float4*)(P + j * QB))[0];
        float4 b = ((float4*)(P + j * QB))[1];
        a.x = __expf(a.x - M[0]); a.y = __expf(a.y - M[1]);
        a.z = __expf(a.z - M[2]); a.w = __expf(a.w - M[3]);
        b.x = __expf(b.x - M[4]); b.y = __expf(b.y - M[5]);
        b.z = __expf(b.z - M[6]); b.w = __expf(b.w - M[7]);
        ls[0] += a.x; ls[1] += a.y; ls[2] += a.z; ls[3] += a.w;
        ls[4] += b.x; ls[5] += b.y; ls[6] += b.z; ls[7] += b.w;
        ((float4*)(P + j * QB))[0] = a;
        ((float4*)(P + j * QB))[1] = b;
    }
    float inv[QB];
#pragma unroll
    for (int r = 0; r < QB; r++) {
        red[tid] = ls[r];
        __syncthreads();
        for (int o = 64; o > 0; o >>= 1) {
            if (tid < o) red[tid] += red[tid + o];
            __syncthreads();
        }
        inv[r] = 1.f / red[0];
        __syncthreads();
    }
    float acc[QB];
#pragma unroll
    for (int r = 0; r < QB; r++) acc[r] = 0.f;
#pragma unroll 4
    for (int j = 0; j < nk; j++) {
        float vv = v[(size_t)j * HH + h * HD + tid];
        float4 a = ((float4*)(P + j * QB))[0];
        float4 b = ((float4*)(P + j * QB))[1];
        acc[0] = fmaf(a.x, vv, acc[0]); acc[1] = fmaf(a.y, vv, acc[1]);
        acc[2] = fmaf(a.z, vv, acc[2]); acc[3] = fmaf(a.w, vv, acc[3]);
        acc[4] = fmaf(b.x, vv, acc[4]); acc[5] = fmaf(b.y, vv, acc[5]);
        acc[6] = fmaf(b.z, vv, acc[6]); acc[7] = fmaf(b.w, vv, acc[7]);
    }
#pragma unroll
    for (int r = 0; r < QB; r++)
        out[(size_t)(t0 + r) * HH + h * HD + tid] =
            (act[r] != 0.f) ? acc[r] * inv[r] : 0.f;
}

// ---------------- top-k radix select machinery ----------------
__device__ __forceinline__ unsigned fkey(float x) {
    unsigned b = __float_as_uint(x);
    return (b & 0x80000000u) ? ~b : (b | 0x80000000u);
}
__device__ __forceinline__ float unfkey(unsigned k) {
    unsigned b = (k & 0x80000000u) ? (k & 0x7fffffffu) : ~k;
    return __uint_as_float(b);
}

__global__ void mlp_thresh_kernel(const float* __restrict__ logits,
                                  float* __restrict__ thr) {
    int row = blockIdx.x;
    const float* lr = logits + (size_t)row * II;
    __shared__ unsigned hist[256];
    __shared__ unsigned sh_sel, sh_kk;
    int tid = threadIdx.x;
    unsigned prefix = 0;
    unsigned kk = MLP_TOPK;
    for (int shift = 24; shift >= 0; shift -= 8) {
        hist[tid] = 0;
        __syncthreads();
        for (int i = tid; i < II; i += 256) {
            unsigned u = fkey(lr[i]);
            bool ok = (shift == 24) || ((u >> (shift + 8)) == prefix);
            if (ok) atomicAdd(&hist[(u >> shift) & 255u], 1u);
        }
        __syncthreads();
        if (tid == 0) {
            unsigned c = 0;
            int sel = 0;
            for (int b = 255; b >= 0; b--) {
                c += hist[b];
                if (c >= kk) { sel = b; break; }
            }
            sh_sel = (unsigned)sel;
            sh_kk = kk - (c - hist[sel]);
        }
        __syncthreads();
        prefix = (prefix << 8) | sh_sel;
        kk = sh_kk;
        __syncthreads();
    }
    if (tid == 0) thr[row] = unfkey(prefix);
}

#define BAND 4e-3f
__global__ void mlp_correct_kernel(float* __restrict__ mlog,
                                   const float* __restrict__ hs,
                                   const float* __restrict__ w,
                                   const float* __restrict__ b,
                                   const float* __restrict__ thr) {
    int row = blockIdx.x;
    int tid = threadIdx.x;
    __shared__ int cnt;
    __shared__ int idxs[1024];
    if (tid == 0) cnt = 0;
    __syncthreads();
    float th = thr[row];
    float* lr = mlog + (size_t)row * II;
    for (int i = tid; i < II; i += 256) {
        if (fabsf(lr[i] - th) <= BAND) {
            int p = atomicAdd(&cnt, 1);
            if (p < 1024) idxs[p] = i;
        }
    }
    __syncthreads();
    int n = cnt < 1024 ? cnt : 1024;
    int warp = tid >> 5, lane = tid & 31;
    const float* hsr = hs + (size_t)row * HH;
    for (int c = warp; c < n; c += 8) {
        int i = idxs[c];
        const float* wr = w + (size_t)i * HH;
        float s = 0.f;
        for (int kk = lane; kk < HH; kk += 32) s += hsr[kk] * wr[kk];
        for (int o = 16; o > 0; o >>= 1) s += __shfl_xor_sync(0xffffffffu, s, o);
        if (lane == 0) lr[i] = s + b[i];
    }
}

__global__ void mlp_topk_kernel(const float* __restrict__ logits,
                                float* __restrict__ mask) {
    int row = blockIdx.x;
    const float* lr = logits + (size_t)row * II;
    __shared__ unsigned hist[256];
    __shared__ unsigned sh_sel, sh_kk;
    __shared__ unsigned sh_cnt[2];
    int tid = threadIdx.x;
    unsigned prefix = 0;
    unsigned kk = MLP_TOPK;
    for (int shift = 24; shift >= 0; shift -= 8) {
        hist[tid] = 0;
        __syncthreads();
        for (int i = tid; i < II; i += 256) {
            unsigned u = fkey(lr[i]);
            bool ok = (shift == 24) || ((u >> (shift + 8)) == prefix);
            if (ok) atomicAdd(&hist[(u >> shift) & 255u], 1u);
        }
        __syncthreads();
        if (tid == 0) {
            unsigned c = 0;
            int sel = 0;
            for (int b = 255; b >= 0; b--) {
                c += hist[b];
                if (c >= kk) { sel = b; break; }
            }
            sh_sel = (unsigned)sel;
            sh_kk = kk - (c - hist[sel]);
        }
        __syncthreads();
        prefix = (prefix << 8) | sh_sel;
        kk = sh_kk;
        __syncthreads();
    }
    unsigned thresh = prefix;
    if (tid < 2) sh_cnt[tid] = 0;
    __syncthreads();
    unsigned lg = 0, le = 0;
    for (int i = tid; i < II; i += 256) {
        unsigned u = fkey(lr[i]);
        if (u > thresh) lg++;
        else if (u == thresh) le++;
    }
    atomicAdd(&sh_cnt[0], lg);
    atomicAdd(&sh_cnt[1], le);
    __syncthreads();
    unsigned g = sh_cnt[0], e = sh_cnt[1];
    float* mr = mask + (size_t)row * II;
    if (g + e == MLP_TOPK) {
        for (int i = tid; i < II; i += 256)
            mr[i] = (fkey(lr[i]) >= thresh) ? 1.f : 0.f;
    } else {
        for (int i = tid; i < II; i += 256)
            mr[i] = (fkey(lr[i]) > thresh) ? 1.f : 0.f;
        __syncthreads();
        if (tid == 0) {
            unsigned quota = MLP_TOPK - g;
            for (int i = 0; i < II && quota > 0; i++) {
                if (fkey(lr[i]) == thresh) { mr[i] = 1.f; quota--; }
            }
        }
    }
}

// ---------------- silu * up * mask ----------------
__global__ void silu_mul_mask_kernel(float* __restrict__ gate,
                                     const float* __restrict__ up,
                                     const float* __restrict__ mask, int n) {
    int i = blockIdx.x * 256 + threadIdx.x;
    if (i < n) {
        float x = gate[i];
        float si = x / (1.f + __expf(-x));
        gate[i] = si * up[i] * mask[i];
    }
}

// ---------------- launch ----------------
extern "C" void kernel_launch(void* const* d_in, const int* in_sizes, int n_in,
                              void* d_out, int out_size) {
    const float* hidden = (const float*)d_in[0];
    const int* amask = (const int*)d_in[1];
    const int* pos = (const int*)d_in[2];
    const float* wq = (const float*)d_in[3];
    const float* wk = (const float*)d_in[4];
    const float* wv = (const float*)d_in[5];
    const float* wo = (const float*)d_in[6];
    const float* w_gate = (const float*)d_in[7];
    const float* w_up = (const float*)d_in[8];
    const float* w_down = (const float*)d_in[9];
    const float* ln1 = (const float*)d_in[10];
    const float* ln2 = (const float*)d_in[11];
    const float* apw = (const float*)d_in[12];
    const float* apb = (const float*)d_in[13];
    const float* mpw = (const float*)d_in[14];
    const float* mpb = (const float*)d_in[15];
    float* out = (float*)d_out;

    float *hs, *q, *k, *v, *attn, *res2, *hlog, *hmask, *mlog, *fcm, *gate, *up,
        *thr;
    cudaGetSymbolAddress((void**)&hs, g_hs);
    cudaGetSymbolAddress((void**)&q, g_q);
    cudaGetSymbolAddress((void**)&k, g_k);
    cudaGetSymbolAddress((void**)&v, g_v);
    cudaGetSymbolAddress((void**)&attn, g_attn);
    cudaGetSymbolAddress((void**)&res2, g_res2);
    cudaGetSymbolAddress((void**)&hlog, g_hlogit);
    cudaGetSymbolAddress((void**)&hmask, g_headmask);
    cudaGetSymbolAddress((void**)&mlog, g_mlogit);
    cudaGetSymbolAddress((void**)&fcm, g_fcmask);
    cudaGetSymbolAddress((void**)&gate, g_gate);
    cudaGetSymbolAddress((void**)&up, g_up);
    cudaGetSymbolAddress((void**)&thr, g_thr);

    const int SMEM_B = 8 * HBUF * (int)sizeof(__nv_bfloat16);   // 81920 B
    cudaFuncSetAttribute(bf16gemm_nt<3>,
                         cudaFuncAttributeMaxDynamicSharedMemorySize, SMEM_B);
    cudaFuncSetAttribute(bf16gemm_nt<4>,
                         cudaFuncAttributeMaxDynamicSharedMemorySize, SMEM_B);
    const int SMEM_A = (QB * HD + TT * QB) * (int)sizeof(float);  // 69632 B
    cudaFuncSetAttribute(attention8_kernel,
                         cudaFuncAttributeMaxDynamicSharedMemorySize, SMEM_A);

    dim3 gHH(HH / 128, TT / 128);
    dim3 gII(II / 128, TT / 128);

    rmsnorm_kernel<<<TT, 256>>>(hidden, ln1, hs);
    bf16gemm_nt<4><<<gHH, 256, SMEM_B>>>(hs, wq, nullptr, nullptr, q, TT, HH, HH);
    bf16gemm_nt<4><<<gHH, 256, SMEM_B>>>(hs, wk, nullptr, nullptr, k, TT, HH, HH);
    bf16gemm_nt<4><<<gHH, 256, SMEM_B>>>(hs, wv, nullptr, nullptr, v, TT, HH, HH);
    rope_kernel<<<(TT * NH * 64 + 255) / 256, 256>>>(q, k, pos);
    attn_pred_kernel<<<TT, 256>>>(hs, apw, apb, hlog);
    head_mask_kernel<<<TT, 32>>>(hlog, hmask);
    attention8_kernel<<<dim3(TT / QB, NH), 128, SMEM_A>>>(q, k, v, hmask, amask,
                                                          attn);
    bf16gemm_nt<4><<<gHH, 256, SMEM_B>>>(attn, wo, nullptr, hidden, res2, TT, HH, HH);
    rmsnorm_kernel<<<TT, 256>>>(res2, ln2, hs);
    bf16gemm_nt<3><<<gII, 256, SMEM_B>>>(hs, mpw, mpb, nullptr, mlog, TT, II, HH);
    mlp_thresh_kernel<<<TT, 256>>>(mlog, thr);
    mlp_correct_kernel<<<TT, 256>>>(mlog, hs, mpw, mpb, thr);
    mlp_topk_kernel<<<TT, 256>>>(mlog, fcm);
    bf16gemm_nt<3><<<gII, 256, SMEM_B>>>(hs, w_gate, nullptr, nullptr, gate, TT, II, HH);
    bf16gemm_nt<3><<<gII, 256, SMEM_B>>>(hs, w_up, nullptr, nullptr, up, TT, II, HH);
    silu_mul_mask_kernel<<<(TT * II + 255) / 256, 256>>>(gate, up, fcm, TT * II);
    bf16gemm_nt<3><<<gHH, 256, SMEM_B>>>(gate, w_down, nullptr, res2, out, TT, HH, II);
}